// round 12
// baseline (speedup 1.0000x reference)
#include <cuda_runtime.h>
#include <cuda_bf16.h>
#include <cstdint>

#define NN 100000
#define EE 1600000
#define ETOT (EE + NN)

// ---------------- scratch (static __device__ — no allocations) ----------------
__device__ uint32_t g_h1b[NN * 32];   // h1 as packed bf16x2 (col pairs)
__device__ uint32_t g_h2b[NN * 64];   // h2 as packed bf16x2 (col pairs)
__device__ float g_as1[NN * 8];
__device__ float g_ad1[NN * 8];
__device__ float g_as2[NN * 8];
__device__ float g_ad2[NN * 8];
__device__ int   g_rowptr[NN + 1];
__device__ int   g_cur[NN];
__device__ int   g_csr[ETOT];
__device__ int   g_bagg[98];
__device__ int   g_cb[4];             // grid-barrier counters (reset by k_prep)
__device__ __nv_bfloat16 g_w1h[64 * 512];
__device__ __nv_bfloat16 g_w1l[64 * 512];
__device__ __nv_bfloat16 g_w2h[128 * 64];
__device__ __nv_bfloat16 g_w2l[128 * 64];
__device__ __nv_bfloat16 g_o1h[NN * 64];
__device__ __nv_bfloat16 g_o1l[NN * 64];

// ---------------- streams/events (static init, before harness checkpoints) -----
struct SideStreams {
    cudaStream_t sA;
    cudaEvent_t e0, eA;
    SideStreams() {
        cudaStreamCreateWithFlags(&sA, cudaStreamNonBlocking);
        cudaEventCreateWithFlags(&e0, cudaEventDisableTiming);
        cudaEventCreateWithFlags(&eA, cudaEventDisableTiming);
    }
};
static SideStreams g_ss;

// ---------------- warp mma ------------------------------------------------------
__device__ __forceinline__ void mma16816(float* c, uint32_t a0, uint32_t a1,
                                         uint32_t a2, uint32_t a3,
                                         uint32_t b0, uint32_t b1) {
    asm volatile(
        "mma.sync.aligned.m16n8k16.row.col.f32.bf16.bf16.f32 "
        "{%0,%1,%2,%3}, {%4,%5,%6,%7}, {%8,%9}, {%0,%1,%2,%3};"
        : "+f"(c[0]), "+f"(c[1]), "+f"(c[2]), "+f"(c[3])
        : "r"(a0), "r"(a1), "r"(a2), "r"(a3), "r"(b0), "r"(b1));
}

// ---------------- prep: weight splits + barrier-counter reset -------------------
__global__ void k_prep(const float* __restrict__ W1, const float* __restrict__ W2) {
    int idx = blockIdx.x * 256 + threadIdx.x;
    if (idx < 4) g_cb[idx] = 0;
    if (idx < 512 * 64) {
        int k = idx >> 6, n = idx & 63;
        float v = W1[idx];
        __nv_bfloat16 h = __float2bfloat16(v);
        g_w1h[n * 512 + k] = h;
        g_w1l[n * 512 + k] = __float2bfloat16(v - __bfloat162float(h));
    }
    if (idx < 64 * 128) {
        int k = idx >> 7, n = idx & 127;
        float v = W2[idx];
        __nv_bfloat16 h = __float2bfloat16(v);
        g_w2h[n * 64 + k] = h;
        g_w2l[n * 64 + k] = __float2bfloat16(v - __bfloat162float(h));
    }
}

// ---------------- fused CSR build (98 all-resident blocks, grid barriers) -------
__device__ __forceinline__ void gbar(int idx) {
    __syncthreads();
    if (threadIdx.x == 0) {
        __threadfence();
        atomicAdd(&g_cb[idx], 1);
        while (atomicAdd(&g_cb[idx], 0) < 98) { }
    }
    __syncthreads();
}

__global__ void __launch_bounds__(1024) k_csr_all(const int* __restrict__ src,
                                                  const int* __restrict__ dst) {
    __shared__ int sh[1024];
    __shared__ int s_excl;
    const int t = threadIdx.x, bid = blockIdx.x;
    const int tid = bid * 1024 + t;
    const int NT = 98 * 1024;

    // phase 0: zero per-node counters
    if (tid < NN) g_cur[tid] = 0;
    gbar(0);

    // phase 1: count (vectorized int4, grid stride)
    for (int e4 = tid; e4 < EE / 4; e4 += NT) {
        int4 d = *(const int4*)(dst + e4 * 4);
        atomicAdd(&g_cur[d.x], 1);
        atomicAdd(&g_cur[d.y], 1);
        atomicAdd(&g_cur[d.z], 1);
        atomicAdd(&g_cur[d.w], 1);
    }
    gbar(1);

    // phase 2: scan (+1 self loop), publish block aggregates, exclusive offsets
    int v = (tid < NN) ? g_cur[tid] + 1 : 0;
    sh[t] = v;
    __syncthreads();
    for (int off = 1; off < 1024; off <<= 1) {
        int a = (t >= off) ? sh[t - off] : 0;
        __syncthreads();
        sh[t] += a;
        __syncthreads();
    }
    int incl = sh[t];
    if (t == 1023) g_bagg[bid] = sh[1023];
    gbar(2);
    if (t < 32) {
        int sum = 0;
        for (int base = 0; base < bid; base += 32) {
            int idx2 = base + t;
            int val = (idx2 < bid) ? g_bagg[idx2] : 0;
#pragma unroll
            for (int o = 16; o; o >>= 1) val += __shfl_xor_sync(0xffffffffu, val, o);
            sum += val;
        }
        if (t == 0) s_excl = sum;
    }
    __syncthreads();
    if (tid < NN) {
        int p = s_excl + incl - v;
        g_rowptr[tid] = p;
        g_csr[p] = tid;      // self loop first
        g_cur[tid] = p + 1;  // cursor
    }
    if (tid == 0) g_rowptr[NN] = ETOT;
    gbar(3);

    // phase 3: scatter
    for (int e4 = tid; e4 < EE / 4; e4 += NT) {
        int4 s = *(const int4*)(src + e4 * 4);
        int4 d = *(const int4*)(dst + e4 * 4);
        g_csr[atomicAdd(&g_cur[d.x], 1)] = s.x;
        g_csr[atomicAdd(&g_cur[d.y], 1)] = s.y;
        g_csr[atomicAdd(&g_cur[d.z], 1)] = s.z;
        g_csr[atomicAdd(&g_cur[d.w], 1)] = s.w;
    }
}

// ---------------- layer-1 GEMM via mma.sync bf16 hi/lo, alpha fused -------------
#define A_HI_OFF 0
#define A_LO_OFF 36864
#define B_HI_OFF 73728
#define B_LO_OFF 82944
#define SM1_TOTAL 92160

__global__ void __launch_bounds__(256) k_gemm1_mma(
    const float* __restrict__ x,
    const __nv_bfloat16* __restrict__ Wh, const __nv_bfloat16* __restrict__ Wl,
    const float* __restrict__ aS, const float* __restrict__ aD) {
    extern __shared__ char smem[];
    const int tid = threadIdx.x;
    const int wid = tid >> 5, lane = tid & 31;
    const int gr = lane >> 2;
    const int kc = (lane & 3) * 2;
    const int m0 = blockIdx.x * 256;
    const int wr = wid * 32;

    float acc[2][8][4];
#pragma unroll
    for (int i = 0; i < 2; i++)
#pragma unroll
        for (int j = 0; j < 8; j++)
#pragma unroll
            for (int q = 0; q < 4; q++) acc[i][j][q] = 0.f;

    for (int kt = 0; kt < 512; kt += 64) {
#pragma unroll
        for (int i = 0; i < 16; i++) {
            int idx = tid + 256 * i;
            int r = idx >> 4, c4 = idx & 15;
            float4 v = make_float4(0.f, 0.f, 0.f, 0.f);
            if (m0 + r < NN)
                v = *(const float4*)(x + (size_t)(m0 + r) * 512 + kt + c4 * 4);
            __nv_bfloat162 h01 = __floats2bfloat162_rn(v.x, v.y);
            __nv_bfloat162 h23 = __floats2bfloat162_rn(v.z, v.w);
            float2 f01 = __bfloat1622float2(h01);
            float2 f23 = __bfloat1622float2(h23);
            __nv_bfloat162 l01 = __floats2bfloat162_rn(v.x - f01.x, v.y - f01.y);
            __nv_bfloat162 l23 = __floats2bfloat162_rn(v.z - f23.x, v.w - f23.y);
            uint32_t off = r * 144 + c4 * 8;
            *(uint2*)(smem + A_HI_OFF + off) =
                make_uint2(*(uint32_t*)&h01, *(uint32_t*)&h23);
            *(uint2*)(smem + A_LO_OFF + off) =
                make_uint2(*(uint32_t*)&l01, *(uint32_t*)&l23);
        }
#pragma unroll
        for (int i = 0; i < 4; i++) {
            int idx = tid + 256 * i;
            int n = idx >> 4, c4 = idx & 15;
            uint32_t off = n * 144 + c4 * 8;
            *(uint2*)(smem + B_HI_OFF + off) = *(const uint2*)(Wh + n * 512 + kt + c4 * 4);
            *(uint2*)(smem + B_LO_OFF + off) = *(const uint2*)(Wl + n * 512 + kt + c4 * 4);
        }
        __syncthreads();
#pragma unroll
        for (int s = 0; s < 4; s++) {
            const int ks = s * 16;
            uint32_t ah[2][4], al[2][4];
#pragma unroll
            for (int i = 0; i < 2; i++) {
                int r0 = wr + i * 16 + gr;
                const char* pa = smem + (r0 * 144 + (ks + kc) * 2);
                ah[i][0] = *(const uint32_t*)(pa + A_HI_OFF);
                ah[i][1] = *(const uint32_t*)(pa + A_HI_OFF + 8 * 144);
                ah[i][2] = *(const uint32_t*)(pa + A_HI_OFF + 16);
                ah[i][3] = *(const uint32_t*)(pa + A_HI_OFF + 8 * 144 + 16);
                al[i][0] = *(const uint32_t*)(pa + A_LO_OFF);
                al[i][1] = *(const uint32_t*)(pa + A_LO_OFF + 8 * 144);
                al[i][2] = *(const uint32_t*)(pa + A_LO_OFF + 16);
                al[i][3] = *(const uint32_t*)(pa + A_LO_OFF + 8 * 144 + 16);
            }
#pragma unroll
            for (int j = 0; j < 8; j++) {
                int n0 = j * 8 + gr;
                const char* pb = smem + (n0 * 144 + (ks + kc) * 2);
                uint32_t bh0 = *(const uint32_t*)(pb + B_HI_OFF);
                uint32_t bh1 = *(const uint32_t*)(pb + B_HI_OFF + 16);
                uint32_t bl0 = *(const uint32_t*)(pb + B_LO_OFF);
                uint32_t bl1 = *(const uint32_t*)(pb + B_LO_OFF + 16);
#pragma unroll
                for (int i = 0; i < 2; i++) {
                    mma16816(acc[i][j], ah[i][0], ah[i][1], ah[i][2], ah[i][3], bh0, bh1);
                    mma16816(acc[i][j], ah[i][0], ah[i][1], ah[i][2], ah[i][3], bl0, bl1);
                    mma16816(acc[i][j], al[i][0], al[i][1], al[i][2], al[i][3], bh0, bh1);
                }
            }
        }
        __syncthreads();
    }

    float* Cs = (float*)smem;
#pragma unroll
    for (int i = 0; i < 2; i++) {
        int r0 = wr + i * 16 + gr;
#pragma unroll
        for (int j = 0; j < 8; j++) {
            int col = j * 8 + kc;
            *(float2*)&Cs[r0 * 72 + col] = make_float2(acc[i][j][0], acc[i][j][1]);
            *(float2*)&Cs[(r0 + 8) * 72 + col] = make_float2(acc[i][j][2], acc[i][j][3]);
        }
    }
    __syncthreads();

    int m = m0 + tid;
    if (m < NN) {
        const float* row = Cs + tid * 72;
#pragma unroll
        for (int c = 0; c < 64; c += 8) {
            __nv_bfloat162 t0 = __floats2bfloat162_rn(row[c + 0], row[c + 1]);
            __nv_bfloat162 t1 = __floats2bfloat162_rn(row[c + 2], row[c + 3]);
            __nv_bfloat162 t2 = __floats2bfloat162_rn(row[c + 4], row[c + 5]);
            __nv_bfloat162 t3 = __floats2bfloat162_rn(row[c + 6], row[c + 7]);
            *(uint4*)(g_h1b + (size_t)m * 32 + c / 2) =
                make_uint4(*(uint32_t*)&t0, *(uint32_t*)&t1,
                           *(uint32_t*)&t2, *(uint32_t*)&t3);
        }
        float s[8], t[8];
#pragma unroll
        for (int h = 0; h < 8; h++) { s[h] = 0.f; t[h] = 0.f; }
#pragma unroll
        for (int h = 0; h < 8; h++)
#pragma unroll
            for (int c = 0; c < 8; c++) {
                float v = row[h * 8 + c];
                s[h] = fmaf(v, aS[h * 8 + c], s[h]);
                t[h] = fmaf(v, aD[h * 8 + c], t[h]);
            }
        *(float4*)(g_as1 + (size_t)m * 8) = make_float4(s[0], s[1], s[2], s[3]);
        *(float4*)(g_as1 + (size_t)m * 8 + 4) = make_float4(s[4], s[5], s[6], s[7]);
        *(float4*)(g_ad1 + (size_t)m * 8) = make_float4(t[0], t[1], t[2], t[3]);
        *(float4*)(g_ad1 + (size_t)m * 8 + 4) = make_float4(t[4], t[5], t[6], t[7]);
    }
}

// ---------------- layer-2 GEMM via mma.sync, alpha fused, h2 -> bf16x2 ----------
#define G2_AH 0
#define G2_AL 18432
#define G2_BH 36864
#define G2_BL 55296
#define G2_TOTAL 73728

__global__ void __launch_bounds__(256) k_gemm2_mma(
    const __nv_bfloat16* __restrict__ Ah, const __nv_bfloat16* __restrict__ Al,
    const __nv_bfloat16* __restrict__ Bh, const __nv_bfloat16* __restrict__ Bl,
    const float* __restrict__ aS, const float* __restrict__ aD) {
    extern __shared__ char smem[];
    const int tid = threadIdx.x;
    const int wid = tid >> 5, lane = tid & 31;
    const int gr = lane >> 2;
    const int kc = (lane & 3) * 2;
    const int wm = wid & 3, wn = wid >> 2;
    const int m0 = blockIdx.x * 128;

#pragma unroll
    for (int i = 0; i < 8; i++) {
        int idx = tid + 256 * i;
        int r = idx >> 4, c4 = idx & 15;
        uint2 vh = make_uint2(0u, 0u), vl = make_uint2(0u, 0u);
        if (m0 + r < NN) {
            vh = *(const uint2*)(Ah + (size_t)(m0 + r) * 64 + c4 * 4);
            vl = *(const uint2*)(Al + (size_t)(m0 + r) * 64 + c4 * 4);
        }
        uint32_t off = r * 144 + c4 * 8;
        *(uint2*)(smem + G2_AH + off) = vh;
        *(uint2*)(smem + G2_AL + off) = vl;
    }
#pragma unroll
    for (int i = 0; i < 8; i++) {
        int idx = tid + 256 * i;
        int n = idx >> 4, c4 = idx & 15;
        uint32_t off = n * 144 + c4 * 8;
        *(uint2*)(smem + G2_BH + off) = *(const uint2*)(Bh + n * 64 + c4 * 4);
        *(uint2*)(smem + G2_BL + off) = *(const uint2*)(Bl + n * 64 + c4 * 4);
    }
    __syncthreads();

    float acc[2][8][4];
#pragma unroll
    for (int i = 0; i < 2; i++)
#pragma unroll
        for (int j = 0; j < 8; j++)
#pragma unroll
            for (int q = 0; q < 4; q++) acc[i][j][q] = 0.f;

#pragma unroll
    for (int s = 0; s < 4; s++) {
        const int ks = s * 16;
        uint32_t ah[2][4], al[2][4];
#pragma unroll
        for (int i = 0; i < 2; i++) {
            int r0 = wm * 32 + i * 16 + gr;
            const char* pa = smem + (r0 * 144 + (ks + kc) * 2);
            ah[i][0] = *(const uint32_t*)(pa + G2_AH);
            ah[i][1] = *(const uint32_t*)(pa + G2_AH + 8 * 144);
            ah[i][2] = *(const uint32_t*)(pa + G2_AH + 16);
            ah[i][3] = *(const uint32_t*)(pa + G2_AH + 8 * 144 + 16);
            al[i][0] = *(const uint32_t*)(pa + G2_AL);
            al[i][1] = *(const uint32_t*)(pa + G2_AL + 8 * 144);
            al[i][2] = *(const uint32_t*)(pa + G2_AL + 16);
            al[i][3] = *(const uint32_t*)(pa + G2_AL + 8 * 144 + 16);
        }
#pragma unroll
        for (int j = 0; j < 8; j++) {
            int n0 = wn * 64 + j * 8 + gr;
            const char* pb = smem + (n0 * 144 + (ks + kc) * 2);
            uint32_t bh0 = *(const uint32_t*)(pb + G2_BH);
            uint32_t bh1 = *(const uint32_t*)(pb + G2_BH + 16);
            uint32_t bl0 = *(const uint32_t*)(pb + G2_BL);
            uint32_t bl1 = *(const uint32_t*)(pb + G2_BL + 16);
#pragma unroll
            for (int i = 0; i < 2; i++) {
                mma16816(acc[i][j], ah[i][0], ah[i][1], ah[i][2], ah[i][3], bh0, bh1);
                mma16816(acc[i][j], ah[i][0], ah[i][1], ah[i][2], ah[i][3], bl0, bl1);
                mma16816(acc[i][j], al[i][0], al[i][1], al[i][2], al[i][3], bh0, bh1);
            }
        }
    }
    __syncthreads();

    float* Cs = (float*)smem;
#pragma unroll
    for (int i = 0; i < 2; i++) {
        int r0 = wm * 32 + i * 16 + gr;
#pragma unroll
        for (int j = 0; j < 8; j++) {
            int col = wn * 64 + j * 8 + kc;
            *(float2*)&Cs[r0 * 132 + col] = make_float2(acc[i][j][0], acc[i][j][1]);
            *(float2*)&Cs[(r0 + 8) * 132 + col] = make_float2(acc[i][j][2], acc[i][j][3]);
        }
    }
    __syncthreads();

    int r = tid >> 1, chalf = (tid & 1) * 64;
    int m = m0 + r;
    if (m < NN) {
        const float* row = Cs + r * 132 + chalf;
#pragma unroll
        for (int c = 0; c < 64; c += 8) {
            __nv_bfloat162 t0 = __floats2bfloat162_rn(row[c + 0], row[c + 1]);
            __nv_bfloat162 t1 = __floats2bfloat162_rn(row[c + 2], row[c + 3]);
            __nv_bfloat162 t2 = __floats2bfloat162_rn(row[c + 4], row[c + 5]);
            __nv_bfloat162 t3 = __floats2bfloat162_rn(row[c + 6], row[c + 7]);
            *(uint4*)(g_h2b + (size_t)m * 64 + (tid & 1) * 32 + c / 2) =
                make_uint4(*(uint32_t*)&t0, *(uint32_t*)&t1,
                           *(uint32_t*)&t2, *(uint32_t*)&t3);
        }
        int hb = (tid & 1) * 4;
        float s[4], t[4];
#pragma unroll
        for (int q = 0; q < 4; q++) { s[q] = 0.f; t[q] = 0.f; }
#pragma unroll
        for (int q = 0; q < 4; q++) {
            int hh = hb + q;
#pragma unroll
            for (int c = 0; c < 16; c++) {
                float v = row[q * 16 + c];
                s[q] = fmaf(v, aS[hh * 16 + c], s[q]);
                t[q] = fmaf(v, aD[hh * 16 + c], t[q]);
            }
        }
        *(float4*)(g_as2 + (size_t)m * 8 + hb) = make_float4(s[0], s[1], s[2], s[3]);
        *(float4*)(g_ad2 + (size_t)m * 8 + hb) = make_float4(t[0], t[1], t[2], t[3]);
    }
}

// ---------------- layer-1 aggregation (bf16 h1, col-pair lanes) -----------------
__global__ void k_agg1(const float* __restrict__ bias, const float* __restrict__ preluw) {
    __shared__ float s_ex[8][32][8];
    __shared__ int s_sr[8][32];
    int warp = threadIdx.x >> 5, lane = threadIdx.x & 31;
    int n = blockIdx.x * 8 + warp;
    if (n >= NN) return;
    int s = g_rowptr[n], e2 = g_rowptr[n + 1];

    float adv[8];
    {
        float4 a0 = *(const float4*)(g_ad1 + n * 8);
        float4 a1 = *(const float4*)(g_ad1 + n * 8 + 4);
        adv[0] = a0.x; adv[1] = a0.y; adv[2] = a0.z; adv[3] = a0.w;
        adv[4] = a1.x; adv[5] = a1.y; adv[6] = a1.z; adv[7] = a1.w;
    }
    float den[8];
#pragma unroll
    for (int k = 0; k < 8; k++) den[k] = 0.f;
    float a0c = 0.f, a1c = 0.f;
    const int hown = lane >> 2;
    for (int base = s; base < e2; base += 32) {
        int idx = base + lane;
        int cnt = min(32, e2 - base);
        int sr = 0;
        float ex[8];
#pragma unroll
        for (int k = 0; k < 8; k++) ex[k] = 0.f;
        if (idx < e2) {
            sr = g_csr[idx];
            float4 a0 = *(const float4*)(g_as1 + sr * 8);
            float4 a1 = *(const float4*)(g_as1 + sr * 8 + 4);
            float av[8] = {a0.x, a0.y, a0.z, a0.w, a1.x, a1.y, a1.z, a1.w};
#pragma unroll
            for (int k = 0; k < 8; k++) {
                float e = av[k] + adv[k];
                e = e >= 0.f ? e : 0.2f * e;
                ex[k] = __expf(e);
                den[k] += ex[k];
            }
        }
        s_sr[warp][lane] = sr;
        *(float4*)&s_ex[warp][lane][0] = make_float4(ex[0], ex[1], ex[2], ex[3]);
        *(float4*)&s_ex[warp][lane][4] = make_float4(ex[4], ex[5], ex[6], ex[7]);
        __syncwarp();
        int cnt4 = (cnt + 3) & ~3;
        for (int j = 0; j < cnt4; j += 4) {
            int s0 = s_sr[warp][j + 0], s1 = s_sr[warp][j + 1];
            int s2 = s_sr[warp][j + 2], s3 = s_sr[warp][j + 3];
            uint32_t q0 = g_h1b[(size_t)s0 * 32 + lane];
            uint32_t q1 = g_h1b[(size_t)s1 * 32 + lane];
            uint32_t q2 = g_h1b[(size_t)s2 * 32 + lane];
            uint32_t q3 = g_h1b[(size_t)s3 * 32 + lane];
            float e0 = s_ex[warp][j + 0][hown];
            float e1 = s_ex[warp][j + 1][hown];
            float e2w = s_ex[warp][j + 2][hown];
            float e3 = s_ex[warp][j + 3][hown];
            float2 f0 = __bfloat1622float2(*(__nv_bfloat162*)&q0);
            float2 f1 = __bfloat1622float2(*(__nv_bfloat162*)&q1);
            float2 f2 = __bfloat1622float2(*(__nv_bfloat162*)&q2);
            float2 f3 = __bfloat1622float2(*(__nv_bfloat162*)&q3);
            a0c = fmaf(e0, f0.x, a0c); a1c = fmaf(e0, f0.y, a1c);
            a0c = fmaf(e1, f1.x, a0c); a1c = fmaf(e1, f1.y, a1c);
            a0c = fmaf(e2w, f2.x, a0c); a1c = fmaf(e2w, f2.y, a1c);
            a0c = fmaf(e3, f3.x, a0c); a1c = fmaf(e3, f3.y, a1c);
        }
        __syncwarp();
    }
#pragma unroll
    for (int k = 0; k < 8; k++)
#pragma unroll
        for (int off = 16; off; off >>= 1)
            den[k] += __shfl_xor_sync(0xffffffffu, den[k], off);

    float d = (hown == 0) ? den[0] : (hown == 1) ? den[1] : (hown == 2) ? den[2]
            : (hown == 3) ? den[3] : (hown == 4) ? den[4] : (hown == 5) ? den[5]
            : (hown == 6) ? den[6] : den[7];
    float pw = *preluw;
    float v0 = a0c / d + bias[2 * lane];
    float v1 = a1c / d + bias[2 * lane + 1];
    v0 = v0 >= 0.f ? v0 : pw * v0;
    v1 = v1 >= 0.f ? v1 : pw * v1;
    __nv_bfloat162 hi = __floats2bfloat162_rn(v0, v1);
    float2 hf = __bfloat1622float2(hi);
    __nv_bfloat162 lo = __floats2bfloat162_rn(v0 - hf.x, v1 - hf.y);
    ((uint32_t*)(g_o1h + (size_t)n * 64))[lane] = *(uint32_t*)&hi;
    ((uint32_t*)(g_o1l + (size_t)n * 64))[lane] = *(uint32_t*)&lo;
}

// ---------------- layer-2 aggregation (bf16 h2) + mean + bias + log_softmax -----
__global__ void k_agg2(const float* __restrict__ bias2, float* __restrict__ out) {
    __shared__ float s_ex[8][32][8];
    __shared__ int s_sr[8][32];
    int warp = threadIdx.x >> 5, lane = threadIdx.x & 31;
    int n = blockIdx.x * 8 + warp;
    if (n >= NN) return;
    int s = g_rowptr[n], e2 = g_rowptr[n + 1];

    float adv[8];
    {
        float4 a0 = *(const float4*)(g_ad2 + n * 8);
        float4 a1 = *(const float4*)(g_ad2 + n * 8 + 4);
        adv[0] = a0.x; adv[1] = a0.y; adv[2] = a0.z; adv[3] = a0.w;
        adv[4] = a1.x; adv[5] = a1.y; adv[6] = a1.z; adv[7] = a1.w;
    }
    float den[8];
#pragma unroll
    for (int k = 0; k < 8; k++) den[k] = 0.f;
    float a00 = 0.f, a01 = 0.f, a10 = 0.f, a11 = 0.f;
    const int ha = lane >> 3, hb = 4 + (lane >> 3);
    for (int base = s; base < e2; base += 32) {
        int idx = base + lane;
        int cnt = min(32, e2 - base);
        int sr = 0;
        float ex[8];
#pragma unroll
        for (int k = 0; k < 8; k++) ex[k] = 0.f;
        if (idx < e2) {
            sr = g_csr[idx];
            float4 a0 = *(const float4*)(g_as2 + sr * 8);
            float4 a1 = *(const float4*)(g_as2 + sr * 8 + 4);
            float av[8] = {a0.x, a0.y, a0.z, a0.w, a1.x, a1.y, a1.z, a1.w};
#pragma unroll
            for (int k = 0; k < 8; k++) {
                float e = av[k] + adv[k];
                e = e >= 0.f ? e : 0.2f * e;
                ex[k] = __expf(e);
                den[k] += ex[k];
            }
        }
        s_sr[warp][lane] = sr;
        *(float4*)&s_ex[warp][lane][0] = make_float4(ex[0], ex[1], ex[2], ex[3]);
        *(float4*)&s_ex[warp][lane][4] = make_float4(ex[4], ex[5], ex[6], ex[7]);
        __syncwarp();
        int cnt4 = (cnt + 3) & ~3;
        for (int j = 0; j < cnt4; j += 4) {
            int s0 = s_sr[warp][j + 0], s1 = s_sr[warp][j + 1];
            int s2 = s_sr[warp][j + 2], s3 = s_sr[warp][j + 3];
            const uint32_t* p0 = g_h2b + (size_t)s0 * 64;
            const uint32_t* p1 = g_h2b + (size_t)s1 * 64;
            const uint32_t* p2 = g_h2b + (size_t)s2 * 64;
            const uint32_t* p3 = g_h2b + (size_t)s3 * 64;
            uint32_t qa0 = p0[lane], qb0 = p0[lane + 32];
            uint32_t qa1 = p1[lane], qb1 = p1[lane + 32];
            uint32_t qa2 = p2[lane], qb2 = p2[lane + 32];
            uint32_t qa3 = p3[lane], qb3 = p3[lane + 32];
            float ea0 = s_ex[warp][j + 0][ha], eb0 = s_ex[warp][j + 0][hb];
            float ea1 = s_ex[warp][j + 1][ha], eb1 = s_ex[warp][j + 1][hb];
            float ea2 = s_ex[warp][j + 2][ha], eb2 = s_ex[warp][j + 2][hb];
            float ea3 = s_ex[warp][j + 3][ha], eb3 = s_ex[warp][j + 3][hb];
            float2 fa0 = __bfloat1622float2(*(__nv_bfloat162*)&qa0);
            float2 fb0 = __bfloat1622float2(*(__nv_bfloat162*)&qb0);
            float2 fa1 = __bfloat1622float2(*(__nv_bfloat162*)&qa1);
            float2 fb1 = __bfloat1622float2(*(__nv_bfloat162*)&qb1);
            float2 fa2 = __bfloat1622float2(*(__nv_bfloat162*)&qa2);
            float2 fb2 = __bfloat1622float2(*(__nv_bfloat162*)&qb2);
            float2 fa3 = __bfloat1622float2(*(__nv_bfloat162*)&qa3);
            float2 fb3 = __bfloat1622float2(*(__nv_bfloat162*)&qb3);
            a00 = fmaf(ea0, fa0.x, a00); a01 = fmaf(ea0, fa0.y, a01);
            a10 = fmaf(eb0, fb0.x, a10); a11 = fmaf(eb0, fb0.y, a11);
            a00 = fmaf(ea1, fa1.x, a00); a01 = fmaf(ea1, fa1.y, a01);
            a10 = fmaf(eb1, fb1.x, a10); a11 = fmaf(eb1, fb1.y, a11);
            a00 = fmaf(ea2, fa2.x, a00); a01 = fmaf(ea2, fa2.y, a01);
            a10 = fmaf(eb2, fb2.x, a10); a11 = fmaf(eb2, fb2.y, a11);
            a00 = fmaf(ea3, fa3.x, a00); a01 = fmaf(ea3, fa3.y, a01);
            a10 = fmaf(eb3, fb3.x, a10); a11 = fmaf(eb3, fb3.y, a11);
        }
        __syncwarp();
    }
#pragma unroll
    for (int k = 0; k < 8; k++)
#pragma unroll
        for (int off = 16; off; off >>= 1)
            den[k] += __shfl_xor_sync(0xffffffffu, den[k], off);

    float da = (lane < 8) ? den[0] : (lane < 16) ? den[1] : (lane < 24) ? den[2] : den[3];
    float db = (lane < 8) ? den[4] : (lane < 16) ? den[5] : (lane < 24) ? den[6] : den[7];
    float v0 = a00 / da + a10 / db;
    float v1 = a01 / da + a11 / db;
    v0 += __shfl_xor_sync(0xffffffffu, v0, 8);
    v0 += __shfl_xor_sync(0xffffffffu, v0, 16);
    v1 += __shfl_xor_sync(0xffffffffu, v1, 8);
    v1 += __shfl_xor_sync(0xffffffffu, v1, 16);
    int cp = lane & 7;
    v0 = v0 * 0.125f + bias2[2 * cp];
    v1 = v1 * 0.125f + bias2[2 * cp + 1];
    float mx = fmaxf(v0, v1);
#pragma unroll
    for (int off = 4; off; off >>= 1) mx = fmaxf(mx, __shfl_xor_sync(0xffffffffu, mx, off));
    float se = __expf(v0 - mx) + __expf(v1 - mx);
#pragma unroll
    for (int off = 4; off; off >>= 1) se += __shfl_xor_sync(0xffffffffu, se, off);
    float ls = __logf(se);
    if (lane < 8)
        *(float2*)(out + (size_t)n * 16 + 2 * cp) =
            make_float2(v0 - mx - ls, v1 - mx - ls);
}

// ---------------- launcher ------------------------------------------------------
extern "C" void kernel_launch(void* const* d_in, const int* in_sizes, int n_in,
                              void* d_out, int out_size) {
    const float* x   = (const float*)d_in[0];
    const int*   ei  = (const int*)d_in[1];
    const float* W1  = (const float*)d_in[2];
    const float* aS1 = (const float*)d_in[3];
    const float* aD1 = (const float*)d_in[4];
    const float* b1  = (const float*)d_in[5];
    const float* pw  = (const float*)d_in[6];
    const float* W2  = (const float*)d_in[7];
    const float* aS2 = (const float*)d_in[8];
    const float* aD2 = (const float*)d_in[9];
    const float* b2  = (const float*)d_in[10];
    float* out = (float*)d_out;

    const int* srcp = ei;
    const int* dstp = ei + EE;

    __nv_bfloat16 *p_w1h, *p_w1l, *p_w2h, *p_w2l, *p_o1h, *p_o1l;
    cudaGetSymbolAddress((void**)&p_w1h, g_w1h);
    cudaGetSymbolAddress((void**)&p_w1l, g_w1l);
    cudaGetSymbolAddress((void**)&p_w2h, g_w2h);
    cudaGetSymbolAddress((void**)&p_w2l, g_w2l);
    cudaGetSymbolAddress((void**)&p_o1h, g_o1h);
    cudaGetSymbolAddress((void**)&p_o1l, g_o1l);

    cudaFuncSetAttribute(k_gemm1_mma, cudaFuncAttributeMaxDynamicSharedMemorySize,
                         SM1_TOTAL);
    cudaFuncSetAttribute(k_gemm2_mma, cudaFuncAttributeMaxDynamicSharedMemorySize,
                         G2_TOTAL);

    // 1: prep (weights split + barrier-counter reset)
    k_prep<<<128, 256>>>(W1, W2);

    // fork: GEMM1 on side stream, fused CSR on default stream
    cudaEventRecord(g_ss.e0, 0);
    cudaStreamWaitEvent(g_ss.sA, g_ss.e0, 0);
    k_gemm1_mma<<<(NN + 255) / 256, 256, SM1_TOTAL, g_ss.sA>>>(x, p_w1h, p_w1l,
                                                               aS1, aD1);   // 2
    cudaEventRecord(g_ss.eA, g_ss.sA);

    k_csr_all<<<98, 1024>>>(srcp, dstp);                                    // 3

    // join: aggregation tail needs both branches
    cudaStreamWaitEvent(0, g_ss.eA, 0);
    k_agg1<<<(NN + 7) / 8, 256>>>(b1, pw);                                  // 4 — profiled
    k_gemm2_mma<<<(NN + 127) / 128, 256, G2_TOTAL>>>(p_o1h, p_o1l, p_w2h, p_w2l,
                                                     aS2, aD2);             // 5
    k_agg2<<<(NN + 7) / 8, 256>>>(b2, out);                                 // 6
}

// round 13
// speedup vs baseline: 1.0043x; 1.0043x over previous
#include <cuda_runtime.h>
#include <cuda_bf16.h>
#include <cstdint>

#define NN 100000
#define EE 1600000
#define ETOT (EE + NN)

// ---------------- scratch (static __device__ — no allocations) ----------------
__device__ uint32_t g_h1b[NN * 32];   // h1 as packed bf16x2 (col pairs)
__device__ uint32_t g_h2b[NN * 64];   // h2 as packed bf16x2 (col pairs)
__device__ float g_as1[NN * 8];
__device__ float g_ad1[NN * 8];
__device__ float g_as2[NN * 8];
__device__ float g_ad2[NN * 8];
__device__ int   g_rowptr[NN + 1];
__device__ int   g_cur[NN];
__device__ int   g_csr[ETOT];
__device__ int   g_bagg[98];
__device__ int   g_cnt;
__device__ __nv_bfloat16 g_w1h[64 * 512];
__device__ __nv_bfloat16 g_w1l[64 * 512];
__device__ __nv_bfloat16 g_w2h[128 * 64];
__device__ __nv_bfloat16 g_w2l[128 * 64];
__device__ __nv_bfloat16 g_o1h[NN * 64];
__device__ __nv_bfloat16 g_o1l[NN * 64];

// ---------------- streams/events (static init, before harness checkpoints) -----
struct SideStreams {
    cudaStream_t sA;
    cudaEvent_t e0, eA;
    SideStreams() {
        cudaStreamCreateWithFlags(&sA, cudaStreamNonBlocking);
        cudaEventCreateWithFlags(&e0, cudaEventDisableTiming);
        cudaEventCreateWithFlags(&eA, cudaEventDisableTiming);
    }
};
static SideStreams g_ss;

// ---------------- warp mma ------------------------------------------------------
__device__ __forceinline__ void mma16816(float* c, uint32_t a0, uint32_t a1,
                                         uint32_t a2, uint32_t a3,
                                         uint32_t b0, uint32_t b1) {
    asm volatile(
        "mma.sync.aligned.m16n8k16.row.col.f32.bf16.bf16.f32 "
        "{%0,%1,%2,%3}, {%4,%5,%6,%7}, {%8,%9}, {%0,%1,%2,%3};"
        : "+f"(c[0]), "+f"(c[1]), "+f"(c[2]), "+f"(c[3])
        : "r"(a0), "r"(a1), "r"(a2), "r"(a3), "r"(b0), "r"(b1));
}

// ---------------- prep: weight splits + counter resets --------------------------
__global__ void k_prep(const float* __restrict__ W1, const float* __restrict__ W2) {
    int idx = blockIdx.x * 256 + threadIdx.x;
    if (idx < NN) g_cur[idx] = 0;
    if (idx == 0) g_cnt = 0;
    if (idx < 512 * 64) {
        int k = idx >> 6, n = idx & 63;
        float v = W1[idx];
        __nv_bfloat16 h = __float2bfloat16(v);
        g_w1h[n * 512 + k] = h;
        g_w1l[n * 512 + k] = __float2bfloat16(v - __bfloat162float(h));
    }
    if (idx < 64 * 128) {
        int k = idx >> 7, n = idx & 127;
        float v = W2[idx];
        __nv_bfloat16 h = __float2bfloat16(v);
        g_w2h[n * 64 + k] = h;
        g_w2l[n * 64 + k] = __float2bfloat16(v - __bfloat162float(h));
    }
}

// ---------------- CSR build (split kernels — proven fastest) --------------------
__global__ void k_count(const int* __restrict__ dst) {
    int e4 = blockIdx.x * blockDim.x + threadIdx.x;
    if (e4 < EE / 4) {
        int4 d = *(const int4*)(dst + e4 * 4);
        atomicAdd(&g_cur[d.x], 1);
        atomicAdd(&g_cur[d.y], 1);
        atomicAdd(&g_cur[d.z], 1);
        atomicAdd(&g_cur[d.w], 1);
    }
}
__global__ void k_scan_lb() {
    __shared__ int sh[1024];
    __shared__ int s_excl;
    int t = threadIdx.x, bid = blockIdx.x;
    int i = bid * 1024 + t;
    int v = (i < NN) ? g_cur[i] + 1 : 0;  // +1 = self loop
    sh[t] = v;
    __syncthreads();
    for (int off = 1; off < 1024; off <<= 1) {
        int a = (t >= off) ? sh[t - off] : 0;
        __syncthreads();
        sh[t] += a;
        __syncthreads();
    }
    int incl = sh[t];
    if (t == 0) {
        g_bagg[bid] = sh[1023];
        __threadfence();
        atomicAdd(&g_cnt, 1);
        while (atomicAdd(&g_cnt, 0) < 98) { }
    }
    __syncthreads();
    if (t < 32) {
        int sum = 0;
        for (int base = 0; base < bid; base += 32) {
            int idx2 = base + t;
            int val = (idx2 < bid) ? g_bagg[idx2] : 0;
#pragma unroll
            for (int o = 16; o; o >>= 1) val += __shfl_xor_sync(0xffffffffu, val, o);
            sum += val;
        }
        if (t == 0) s_excl = sum;
    }
    __syncthreads();
    if (i < NN) {
        int p = s_excl + incl - v;
        g_rowptr[i] = p;
        g_csr[p] = i;
        g_cur[i] = p + 1;
    }
    if (i == 0) g_rowptr[NN] = ETOT;
}
__global__ void k_scatter(const int* __restrict__ src, const int* __restrict__ dst) {
    int e4 = blockIdx.x * blockDim.x + threadIdx.x;
    if (e4 < EE / 4) {
        int4 s = *(const int4*)(src + e4 * 4);
        int4 d = *(const int4*)(dst + e4 * 4);
        g_csr[atomicAdd(&g_cur[d.x], 1)] = s.x;
        g_csr[atomicAdd(&g_cur[d.y], 1)] = s.y;
        g_csr[atomicAdd(&g_cur[d.z], 1)] = s.z;
        g_csr[atomicAdd(&g_cur[d.w], 1)] = s.w;
    }
}

// ---------------- layer-1 GEMM via mma.sync bf16 hi/lo, alpha fused -------------
#define A_HI_OFF 0
#define A_LO_OFF 36864
#define B_HI_OFF 73728
#define B_LO_OFF 82944
#define SM1_TOTAL 92160

__global__ void __launch_bounds__(256) k_gemm1_mma(
    const float* __restrict__ x,
    const __nv_bfloat16* __restrict__ Wh, const __nv_bfloat16* __restrict__ Wl,
    const float* __restrict__ aS, const float* __restrict__ aD) {
    extern __shared__ char smem[];
    const int tid = threadIdx.x;
    const int wid = tid >> 5, lane = tid & 31;
    const int gr = lane >> 2;
    const int kc = (lane & 3) * 2;
    const int m0 = blockIdx.x * 256;
    const int wr = wid * 32;

    float acc[2][8][4];
#pragma unroll
    for (int i = 0; i < 2; i++)
#pragma unroll
        for (int j = 0; j < 8; j++)
#pragma unroll
            for (int q = 0; q < 4; q++) acc[i][j][q] = 0.f;

    for (int kt = 0; kt < 512; kt += 64) {
#pragma unroll
        for (int i = 0; i < 16; i++) {
            int idx = tid + 256 * i;
            int r = idx >> 4, c4 = idx & 15;
            float4 v = make_float4(0.f, 0.f, 0.f, 0.f);
            if (m0 + r < NN)
                v = *(const float4*)(x + (size_t)(m0 + r) * 512 + kt + c4 * 4);
            __nv_bfloat162 h01 = __floats2bfloat162_rn(v.x, v.y);
            __nv_bfloat162 h23 = __floats2bfloat162_rn(v.z, v.w);
            float2 f01 = __bfloat1622float2(h01);
            float2 f23 = __bfloat1622float2(h23);
            __nv_bfloat162 l01 = __floats2bfloat162_rn(v.x - f01.x, v.y - f01.y);
            __nv_bfloat162 l23 = __floats2bfloat162_rn(v.z - f23.x, v.w - f23.y);
            uint32_t off = r * 144 + c4 * 8;
            *(uint2*)(smem + A_HI_OFF + off) =
                make_uint2(*(uint32_t*)&h01, *(uint32_t*)&h23);
            *(uint2*)(smem + A_LO_OFF + off) =
                make_uint2(*(uint32_t*)&l01, *(uint32_t*)&l23);
        }
#pragma unroll
        for (int i = 0; i < 4; i++) {
            int idx = tid + 256 * i;
            int n = idx >> 4, c4 = idx & 15;
            uint32_t off = n * 144 + c4 * 8;
            *(uint2*)(smem + B_HI_OFF + off) = *(const uint2*)(Wh + n * 512 + kt + c4 * 4);
            *(uint2*)(smem + B_LO_OFF + off) = *(const uint2*)(Wl + n * 512 + kt + c4 * 4);
        }
        __syncthreads();
#pragma unroll
        for (int s = 0; s < 4; s++) {
            const int ks = s * 16;
            uint32_t ah[2][4], al[2][4];
#pragma unroll
            for (int i = 0; i < 2; i++) {
                int r0 = wr + i * 16 + gr;
                const char* pa = smem + (r0 * 144 + (ks + kc) * 2);
                ah[i][0] = *(const uint32_t*)(pa + A_HI_OFF);
                ah[i][1] = *(const uint32_t*)(pa + A_HI_OFF + 8 * 144);
                ah[i][2] = *(const uint32_t*)(pa + A_HI_OFF + 16);
                ah[i][3] = *(const uint32_t*)(pa + A_HI_OFF + 8 * 144 + 16);
                al[i][0] = *(const uint32_t*)(pa + A_LO_OFF);
                al[i][1] = *(const uint32_t*)(pa + A_LO_OFF + 8 * 144);
                al[i][2] = *(const uint32_t*)(pa + A_LO_OFF + 16);
                al[i][3] = *(const uint32_t*)(pa + A_LO_OFF + 8 * 144 + 16);
            }
#pragma unroll
            for (int j = 0; j < 8; j++) {
                int n0 = j * 8 + gr;
                const char* pb = smem + (n0 * 144 + (ks + kc) * 2);
                uint32_t bh0 = *(const uint32_t*)(pb + B_HI_OFF);
                uint32_t bh1 = *(const uint32_t*)(pb + B_HI_OFF + 16);
                uint32_t bl0 = *(const uint32_t*)(pb + B_LO_OFF);
                uint32_t bl1 = *(const uint32_t*)(pb + B_LO_OFF + 16);
#pragma unroll
                for (int i = 0; i < 2; i++) {
                    mma16816(acc[i][j], ah[i][0], ah[i][1], ah[i][2], ah[i][3], bh0, bh1);
                    mma16816(acc[i][j], ah[i][0], ah[i][1], ah[i][2], ah[i][3], bl0, bl1);
                    mma16816(acc[i][j], al[i][0], al[i][1], al[i][2], al[i][3], bh0, bh1);
                }
            }
        }
        __syncthreads();
    }

    float* Cs = (float*)smem;
#pragma unroll
    for (int i = 0; i < 2; i++) {
        int r0 = wr + i * 16 + gr;
#pragma unroll
        for (int j = 0; j < 8; j++) {
            int col = j * 8 + kc;
            *(float2*)&Cs[r0 * 72 + col] = make_float2(acc[i][j][0], acc[i][j][1]);
            *(float2*)&Cs[(r0 + 8) * 72 + col] = make_float2(acc[i][j][2], acc[i][j][3]);
        }
    }
    __syncthreads();

    int m = m0 + tid;
    if (m < NN) {
        const float* row = Cs + tid * 72;
#pragma unroll
        for (int c = 0; c < 64; c += 8) {
            __nv_bfloat162 t0 = __floats2bfloat162_rn(row[c + 0], row[c + 1]);
            __nv_bfloat162 t1 = __floats2bfloat162_rn(row[c + 2], row[c + 3]);
            __nv_bfloat162 t2 = __floats2bfloat162_rn(row[c + 4], row[c + 5]);
            __nv_bfloat162 t3 = __floats2bfloat162_rn(row[c + 6], row[c + 7]);
            *(uint4*)(g_h1b + (size_t)m * 32 + c / 2) =
                make_uint4(*(uint32_t*)&t0, *(uint32_t*)&t1,
                           *(uint32_t*)&t2, *(uint32_t*)&t3);
        }
        float s[8], t[8];
#pragma unroll
        for (int h = 0; h < 8; h++) { s[h] = 0.f; t[h] = 0.f; }
#pragma unroll
        for (int h = 0; h < 8; h++)
#pragma unroll
            for (int c = 0; c < 8; c++) {
                float v = row[h * 8 + c];
                s[h] = fmaf(v, aS[h * 8 + c], s[h]);
                t[h] = fmaf(v, aD[h * 8 + c], t[h]);
            }
        *(float4*)(g_as1 + (size_t)m * 8) = make_float4(s[0], s[1], s[2], s[3]);
        *(float4*)(g_as1 + (size_t)m * 8 + 4) = make_float4(s[4], s[5], s[6], s[7]);
        *(float4*)(g_ad1 + (size_t)m * 8) = make_float4(t[0], t[1], t[2], t[3]);
        *(float4*)(g_ad1 + (size_t)m * 8 + 4) = make_float4(t[4], t[5], t[6], t[7]);
    }
}

// ---------------- layer-2 GEMM via mma.sync, alpha fused, h2 -> bf16x2 ----------
#define G2_AH 0
#define G2_AL 18432
#define G2_BH 36864
#define G2_BL 55296
#define G2_TOTAL 73728

__global__ void __launch_bounds__(256) k_gemm2_mma(
    const __nv_bfloat16* __restrict__ Ah, const __nv_bfloat16* __restrict__ Al,
    const __nv_bfloat16* __restrict__ Bh, const __nv_bfloat16* __restrict__ Bl,
    const float* __restrict__ aS, const float* __restrict__ aD) {
    extern __shared__ char smem[];
    const int tid = threadIdx.x;
    const int wid = tid >> 5, lane = tid & 31;
    const int gr = lane >> 2;
    const int kc = (lane & 3) * 2;
    const int wm = wid & 3, wn = wid >> 2;
    const int m0 = blockIdx.x * 128;

#pragma unroll
    for (int i = 0; i < 8; i++) {
        int idx = tid + 256 * i;
        int r = idx >> 4, c4 = idx & 15;
        uint2 vh = make_uint2(0u, 0u), vl = make_uint2(0u, 0u);
        if (m0 + r < NN) {
            vh = *(const uint2*)(Ah + (size_t)(m0 + r) * 64 + c4 * 4);
            vl = *(const uint2*)(Al + (size_t)(m0 + r) * 64 + c4 * 4);
        }
        uint32_t off = r * 144 + c4 * 8;
        *(uint2*)(smem + G2_AH + off) = vh;
        *(uint2*)(smem + G2_AL + off) = vl;
    }
#pragma unroll
    for (int i = 0; i < 8; i++) {
        int idx = tid + 256 * i;
        int n = idx >> 4, c4 = idx & 15;
        uint32_t off = n * 144 + c4 * 8;
        *(uint2*)(smem + G2_BH + off) = *(const uint2*)(Bh + n * 64 + c4 * 4);
        *(uint2*)(smem + G2_BL + off) = *(const uint2*)(Bl + n * 64 + c4 * 4);
    }
    __syncthreads();

    float acc[2][8][4];
#pragma unroll
    for (int i = 0; i < 2; i++)
#pragma unroll
        for (int j = 0; j < 8; j++)
#pragma unroll
            for (int q = 0; q < 4; q++) acc[i][j][q] = 0.f;

#pragma unroll
    for (int s = 0; s < 4; s++) {
        const int ks = s * 16;
        uint32_t ah[2][4], al[2][4];
#pragma unroll
        for (int i = 0; i < 2; i++) {
            int r0 = wm * 32 + i * 16 + gr;
            const char* pa = smem + (r0 * 144 + (ks + kc) * 2);
            ah[i][0] = *(const uint32_t*)(pa + G2_AH);
            ah[i][1] = *(const uint32_t*)(pa + G2_AH + 8 * 144);
            ah[i][2] = *(const uint32_t*)(pa + G2_AH + 16);
            ah[i][3] = *(const uint32_t*)(pa + G2_AH + 8 * 144 + 16);
            al[i][0] = *(const uint32_t*)(pa + G2_AL);
            al[i][1] = *(const uint32_t*)(pa + G2_AL + 8 * 144);
            al[i][2] = *(const uint32_t*)(pa + G2_AL + 16);
            al[i][3] = *(const uint32_t*)(pa + G2_AL + 8 * 144 + 16);
        }
#pragma unroll
        for (int j = 0; j < 8; j++) {
            int n0 = wn * 64 + j * 8 + gr;
            const char* pb = smem + (n0 * 144 + (ks + kc) * 2);
            uint32_t bh0 = *(const uint32_t*)(pb + G2_BH);
            uint32_t bh1 = *(const uint32_t*)(pb + G2_BH + 16);
            uint32_t bl0 = *(const uint32_t*)(pb + G2_BL);
            uint32_t bl1 = *(const uint32_t*)(pb + G2_BL + 16);
#pragma unroll
            for (int i = 0; i < 2; i++) {
                mma16816(acc[i][j], ah[i][0], ah[i][1], ah[i][2], ah[i][3], bh0, bh1);
                mma16816(acc[i][j], ah[i][0], ah[i][1], ah[i][2], ah[i][3], bl0, bl1);
                mma16816(acc[i][j], al[i][0], al[i][1], al[i][2], al[i][3], bh0, bh1);
            }
        }
    }
    __syncthreads();

    float* Cs = (float*)smem;
#pragma unroll
    for (int i = 0; i < 2; i++) {
        int r0 = wm * 32 + i * 16 + gr;
#pragma unroll
        for (int j = 0; j < 8; j++) {
            int col = wn * 64 + j * 8 + kc;
            *(float2*)&Cs[r0 * 132 + col] = make_float2(acc[i][j][0], acc[i][j][1]);
            *(float2*)&Cs[(r0 + 8) * 132 + col] = make_float2(acc[i][j][2], acc[i][j][3]);
        }
    }
    __syncthreads();

    int r = tid >> 1, chalf = (tid & 1) * 64;
    int m = m0 + r;
    if (m < NN) {
        const float* row = Cs + r * 132 + chalf;
#pragma unroll
        for (int c = 0; c < 64; c += 8) {
            __nv_bfloat162 t0 = __floats2bfloat162_rn(row[c + 0], row[c + 1]);
            __nv_bfloat162 t1 = __floats2bfloat162_rn(row[c + 2], row[c + 3]);
            __nv_bfloat162 t2 = __floats2bfloat162_rn(row[c + 4], row[c + 5]);
            __nv_bfloat162 t3 = __floats2bfloat162_rn(row[c + 6], row[c + 7]);
            *(uint4*)(g_h2b + (size_t)m * 64 + (tid & 1) * 32 + c / 2) =
                make_uint4(*(uint32_t*)&t0, *(uint32_t*)&t1,
                           *(uint32_t*)&t2, *(uint32_t*)&t3);
        }
        int hb = (tid & 1) * 4;
        float s[4], t[4];
#pragma unroll
        for (int q = 0; q < 4; q++) { s[q] = 0.f; t[q] = 0.f; }
#pragma unroll
        for (int q = 0; q < 4; q++) {
            int hh = hb + q;
#pragma unroll
            for (int c = 0; c < 16; c++) {
                float v = row[q * 16 + c];
                s[q] = fmaf(v, aS[hh * 16 + c], s[q]);
                t[q] = fmaf(v, aD[hh * 16 + c], t[q]);
            }
        }
        *(float4*)(g_as2 + (size_t)m * 8 + hb) = make_float4(s[0], s[1], s[2], s[3]);
        *(float4*)(g_ad2 + (size_t)m * 8 + hb) = make_float4(t[0], t[1], t[2], t[3]);
    }
}

// ---------------- layer-1 aggregation (uint2 gathers, edge-parity lanes) --------
__global__ void k_agg1(const float* __restrict__ bias, const float* __restrict__ preluw) {
    __shared__ float s_ex[8][32][8];
    __shared__ int s_sr[8][32];
    int warp = threadIdx.x >> 5, lane = threadIdx.x & 31;
    int n = blockIdx.x * 8 + warp;
    if (n >= NN) return;
    int s = g_rowptr[n], e2 = g_rowptr[n + 1];

    float adv[8];
    {
        float4 a0 = *(const float4*)(g_ad1 + n * 8);
        float4 a1 = *(const float4*)(g_ad1 + n * 8 + 4);
        adv[0] = a0.x; adv[1] = a0.y; adv[2] = a0.z; adv[3] = a0.w;
        adv[4] = a1.x; adv[5] = a1.y; adv[6] = a1.z; adv[7] = a1.w;
    }
    float den[8];
#pragma unroll
    for (int k = 0; k < 8; k++) den[k] = 0.f;
    // lane owns cols 4*cg..4*cg+3 for edges of parity par
    float acc[4] = {0.f, 0.f, 0.f, 0.f};
    const int par = lane >> 4;
    const int cg = lane & 15;
    const int hw = cg >> 1;
    for (int base = s; base < e2; base += 32) {
        int idx = base + lane;
        int cnt = min(32, e2 - base);
        int sr = 0;
        float ex[8];
#pragma unroll
        for (int k = 0; k < 8; k++) ex[k] = 0.f;
        if (idx < e2) {
            sr = g_csr[idx];
            float4 a0 = *(const float4*)(g_as1 + sr * 8);
            float4 a1 = *(const float4*)(g_as1 + sr * 8 + 4);
            float av[8] = {a0.x, a0.y, a0.z, a0.w, a1.x, a1.y, a1.z, a1.w};
#pragma unroll
            for (int k = 0; k < 8; k++) {
                float e = av[k] + adv[k];
                e = e >= 0.f ? e : 0.2f * e;
                ex[k] = __expf(e);
                den[k] += ex[k];
            }
        }
        s_sr[warp][lane] = sr;
        *(float4*)&s_ex[warp][lane][0] = make_float4(ex[0], ex[1], ex[2], ex[3]);
        *(float4*)&s_ex[warp][lane][4] = make_float4(ex[4], ex[5], ex[6], ex[7]);
        __syncwarp();
        int cnt8 = (cnt + 7) & ~7;   // slots [cnt,32) hold ex=0 — safe padding
        for (int j = 0; j < cnt8; j += 8) {
            int e0 = j + par, e1 = j + 2 + par, e2i = j + 4 + par, e3 = j + 6 + par;
            int t0 = s_sr[warp][e0], t1 = s_sr[warp][e1];
            int t2 = s_sr[warp][e2i], t3 = s_sr[warp][e3];
            uint2 q0 = *(const uint2*)(g_h1b + (size_t)t0 * 32 + cg * 2);
            uint2 q1 = *(const uint2*)(g_h1b + (size_t)t1 * 32 + cg * 2);
            uint2 q2 = *(const uint2*)(g_h1b + (size_t)t2 * 32 + cg * 2);
            uint2 q3 = *(const uint2*)(g_h1b + (size_t)t3 * 32 + cg * 2);
            float x0 = s_ex[warp][e0][hw], x1 = s_ex[warp][e1][hw];
            float x2 = s_ex[warp][e2i][hw], x3 = s_ex[warp][e3][hw];
            float2 fa, fb;
            fa = __bfloat1622float2(*(__nv_bfloat162*)&q0.x);
            fb = __bfloat1622float2(*(__nv_bfloat162*)&q0.y);
            acc[0] = fmaf(x0, fa.x, acc[0]); acc[1] = fmaf(x0, fa.y, acc[1]);
            acc[2] = fmaf(x0, fb.x, acc[2]); acc[3] = fmaf(x0, fb.y, acc[3]);
            fa = __bfloat1622float2(*(__nv_bfloat162*)&q1.x);
            fb = __bfloat1622float2(*(__nv_bfloat162*)&q1.y);
            acc[0] = fmaf(x1, fa.x, acc[0]); acc[1] = fmaf(x1, fa.y, acc[1]);
            acc[2] = fmaf(x1, fb.x, acc[2]); acc[3] = fmaf(x1, fb.y, acc[3]);
            fa = __bfloat1622float2(*(__nv_bfloat162*)&q2.x);
            fb = __bfloat1622float2(*(__nv_bfloat162*)&q2.y);
            acc[0] = fmaf(x2, fa.x, acc[0]); acc[1] = fmaf(x2, fa.y, acc[1]);
            acc[2] = fmaf(x2, fb.x, acc[2]); acc[3] = fmaf(x2, fb.y, acc[3]);
            fa = __bfloat1622float2(*(__nv_bfloat162*)&q3.x);
            fb = __bfloat1622float2(*(__nv_bfloat162*)&q3.y);
            acc[0] = fmaf(x3, fa.x, acc[0]); acc[1] = fmaf(x3, fa.y, acc[1]);
            acc[2] = fmaf(x3, fb.x, acc[2]); acc[3] = fmaf(x3, fb.y, acc[3]);
        }
        __syncwarp();
    }
#pragma unroll
    for (int k = 0; k < 8; k++)
#pragma unroll
        for (int off = 16; off; off >>= 1)
            den[k] += __shfl_xor_sync(0xffffffffu, den[k], off);
    // combine parity halves
#pragma unroll
    for (int q = 0; q < 4; q++)
        acc[q] += __shfl_xor_sync(0xffffffffu, acc[q], 16);

    float d = (hw == 0) ? den[0] : (hw == 1) ? den[1] : (hw == 2) ? den[2]
            : (hw == 3) ? den[3] : (hw == 4) ? den[4] : (hw == 5) ? den[5]
            : (hw == 6) ? den[6] : den[7];
    float pw = *preluw;
    float v[4];
#pragma unroll
    for (int q = 0; q < 4; q++) {
        v[q] = acc[q] / d + bias[4 * cg + q];
        v[q] = v[q] >= 0.f ? v[q] : pw * v[q];
    }
    __nv_bfloat162 h0 = __floats2bfloat162_rn(v[0], v[1]);
    __nv_bfloat162 h1 = __floats2bfloat162_rn(v[2], v[3]);
    float2 f0 = __bfloat1622float2(h0);
    float2 f1 = __bfloat1622float2(h1);
    __nv_bfloat162 l0 = __floats2bfloat162_rn(v[0] - f0.x, v[1] - f0.y);
    __nv_bfloat162 l1 = __floats2bfloat162_rn(v[2] - f1.x, v[3] - f1.y);
    if (lane < 16) {
        *(uint2*)((uint32_t*)(g_o1h + (size_t)n * 64) + 2 * cg) =
            make_uint2(*(uint32_t*)&h0, *(uint32_t*)&h1);
        *(uint2*)((uint32_t*)(g_o1l + (size_t)n * 64) + 2 * cg) =
            make_uint2(*(uint32_t*)&l0, *(uint32_t*)&l1);
    }
}

// ---------------- layer-2 aggregation (uint2 gathers, full-row lanes) -----------
__global__ void k_agg2(const float* __restrict__ bias2, float* __restrict__ out) {
    __shared__ float s_ex[8][32][8];
    __shared__ int s_sr[8][32];
    int warp = threadIdx.x >> 5, lane = threadIdx.x & 31;
    int n = blockIdx.x * 8 + warp;
    if (n >= NN) return;
    int s = g_rowptr[n], e2 = g_rowptr[n + 1];

    float adv[8];
    {
        float4 a0 = *(const float4*)(g_ad2 + n * 8);
        float4 a1 = *(const float4*)(g_ad2 + n * 8 + 4);
        adv[0] = a0.x; adv[1] = a0.y; adv[2] = a0.z; adv[3] = a0.w;
        adv[4] = a1.x; adv[5] = a1.y; adv[6] = a1.z; adv[7] = a1.w;
    }
    float den[8];
#pragma unroll
    for (int k = 0; k < 8; k++) den[k] = 0.f;
    // lane owns cols 4*lane..4*lane+3 (head = lane>>2) for ALL edges
    float acc[4] = {0.f, 0.f, 0.f, 0.f};
    const int hw = lane >> 2;
    for (int base = s; base < e2; base += 32) {
        int idx = base + lane;
        int cnt = min(32, e2 - base);
        int sr = 0;
        float ex[8];
#pragma unroll
        for (int k = 0; k < 8; k++) ex[k] = 0.f;
        if (idx < e2) {
            sr = g_csr[idx];
            float4 a0 = *(const float4*)(g_as2 + sr * 8);
            float4 a1 = *(const float4*)(g_as2 + sr * 8 + 4);
            float av[8] = {a0.x, a0.y, a0.z, a0.w, a1.x, a1.y, a1.z, a1.w};
#pragma unroll
            for (int k = 0; k < 8; k++) {
                float e = av[k] + adv[k];
                e = e >= 0.f ? e : 0.2f * e;
                ex[k] = __expf(e);
                den[k] += ex[k];
            }
        }
        s_sr[warp][lane] = sr;
        *(float4*)&s_ex[warp][lane][0] = make_float4(ex[0], ex[1], ex[2], ex[3]);
        *(float4*)&s_ex[warp][lane][4] = make_float4(ex[4], ex[5], ex[6], ex[7]);
        __syncwarp();
        int cnt4 = (cnt + 3) & ~3;
        for (int j = 0; j < cnt4; j += 4) {
            int t0 = s_sr[warp][j + 0], t1 = s_sr[warp][j + 1];
            int t2 = s_sr[warp][j + 2], t3 = s_sr[warp][j + 3];
            uint2 q0 = *(const uint2*)(g_h2b + (size_t)t0 * 64 + 2 * lane);
            uint2 q1 = *(const uint2*)(g_h2b + (size_t)t1 * 64 + 2 * lane);
            uint2 q2 = *(const uint2*)(g_h2b + (size_t)t2 * 64 + 2 * lane);
            uint2 q3 = *(const uint2*)(g_h2b + (size_t)t3 * 64 + 2 * lane);
            float x0 = s_ex[warp][j + 0][hw], x1 = s_ex[warp][j + 1][hw];
            float x2 = s_ex[warp][j + 2][hw], x3 = s_ex[warp][j + 3][hw];
            float2 fa, fb;
            fa = __bfloat1622float2(*(__nv_bfloat162*)&q0.x);
            fb = __bfloat1622float2(*(__nv_bfloat162*)&q0.y);
            acc[0] = fmaf(x0, fa.x, acc[0]); acc[1] = fmaf(x0, fa.y, acc[1]);
            acc[2] = fmaf(x0, fb.x, acc[2]); acc[3] = fmaf(x0, fb.y, acc[3]);
            fa = __bfloat1622float2(*(__nv_bfloat162*)&q1.x);
            fb = __bfloat1622float2(*(__nv_bfloat162*)&q1.y);
            acc[0] = fmaf(x1, fa.x, acc[0]); acc[1] = fmaf(x1, fa.y, acc[1]);
            acc[2] = fmaf(x1, fb.x, acc[2]); acc[3] = fmaf(x1, fb.y, acc[3]);
            fa = __bfloat1622float2(*(__nv_bfloat162*)&q2.x);
            fb = __bfloat1622float2(*(__nv_bfloat162*)&q2.y);
            acc[0] = fmaf(x2, fa.x, acc[0]); acc[1] = fmaf(x2, fa.y, acc[1]);
            acc[2] = fmaf(x2, fb.x, acc[2]); acc[3] = fmaf(x2, fb.y, acc[3]);
            fa = __bfloat1622float2(*(__nv_bfloat162*)&q3.x);
            fb = __bfloat1622float2(*(__nv_bfloat162*)&q3.y);
            acc[0] = fmaf(x3, fa.x, acc[0]); acc[1] = fmaf(x3, fa.y, acc[1]);
            acc[2] = fmaf(x3, fb.x, acc[2]); acc[3] = fmaf(x3, fb.y, acc[3]);
        }
        __syncwarp();
    }
#pragma unroll
    for (int k = 0; k < 8; k++)
#pragma unroll
        for (int off = 16; off; off >>= 1)
            den[k] += __shfl_xor_sync(0xffffffffu, den[k], off);

    float d = (hw == 0) ? den[0] : (hw == 1) ? den[1] : (hw == 2) ? den[2]
            : (hw == 3) ? den[3] : (hw == 4) ? den[4] : (hw == 5) ? den[5]
            : (hw == 6) ? den[6] : den[7];
    float v[4];
#pragma unroll
    for (int q = 0; q < 4; q++) v[q] = acc[q] / d;
    // mean over heads: lanes {l, l+4, ..., l+28} hold the 8 heads of class group l&3
#pragma unroll
    for (int q = 0; q < 4; q++) {
        v[q] += __shfl_xor_sync(0xffffffffu, v[q], 4);
        v[q] += __shfl_xor_sync(0xffffffffu, v[q], 8);
        v[q] += __shfl_xor_sync(0xffffffffu, v[q], 16);
    }
    int cg = lane & 3;
#pragma unroll
    for (int q = 0; q < 4; q++) v[q] = v[q] * 0.125f + bias2[4 * cg + q];
    // log_softmax over 16 classes spread over 4-lane clusters x 4 each
    float mx = fmaxf(fmaxf(v[0], v[1]), fmaxf(v[2], v[3]));
    mx = fmaxf(mx, __shfl_xor_sync(0xffffffffu, mx, 1));
    mx = fmaxf(mx, __shfl_xor_sync(0xffffffffu, mx, 2));
    float se = __expf(v[0] - mx) + __expf(v[1] - mx) +
               __expf(v[2] - mx) + __expf(v[3] - mx);
    se += __shfl_xor_sync(0xffffffffu, se, 1);
    se += __shfl_xor_sync(0xffffffffu, se, 2);
    float ls = __logf(se);
    if (lane < 4)
        *(float4*)(out + (size_t)n * 16 + 4 * cg) =
            make_float4(v[0] - mx - ls, v[1] - mx - ls,
                        v[2] - mx - ls, v[3] - mx - ls);
}

// ---------------- launcher ------------------------------------------------------
extern "C" void kernel_launch(void* const* d_in, const int* in_sizes, int n_in,
                              void* d_out, int out_size) {
    const float* x   = (const float*)d_in[0];
    const int*   ei  = (const int*)d_in[1];
    const float* W1  = (const float*)d_in[2];
    const float* aS1 = (const float*)d_in[3];
    const float* aD1 = (const float*)d_in[4];
    const float* b1  = (const float*)d_in[5];
    const float* pw  = (const float*)d_in[6];
    const float* W2  = (const float*)d_in[7];
    const float* aS2 = (const float*)d_in[8];
    const float* aD2 = (const float*)d_in[9];
    const float* b2  = (const float*)d_in[10];
    float* out = (float*)d_out;

    const int* srcp = ei;
    const int* dstp = ei + EE;

    __nv_bfloat16 *p_w1h, *p_w1l, *p_w2h, *p_w2l, *p_o1h, *p_o1l;
    cudaGetSymbolAddress((void**)&p_w1h, g_w1h);
    cudaGetSymbolAddress((void**)&p_w1l, g_w1l);
    cudaGetSymbolAddress((void**)&p_w2h, g_w2h);
    cudaGetSymbolAddress((void**)&p_w2l, g_w2l);
    cudaGetSymbolAddress((void**)&p_o1h, g_o1h);
    cudaGetSymbolAddress((void**)&p_o1l, g_o1l);

    cudaFuncSetAttribute(k_gemm1_mma, cudaFuncAttributeMaxDynamicSharedMemorySize,
                         SM1_TOTAL);
    cudaFuncSetAttribute(k_gemm2_mma, cudaFuncAttributeMaxDynamicSharedMemorySize,
                         G2_TOTAL);

    // 1: prep (weights split + counter resets)
    k_prep<<<(NN + 255) / 256, 256>>>(W1, W2);

    // fork: GEMM1 on side stream, split CSR build on default stream
    cudaEventRecord(g_ss.e0, 0);
    cudaStreamWaitEvent(g_ss.sA, g_ss.e0, 0);
    k_gemm1_mma<<<(NN + 255) / 256, 256, SM1_TOTAL, g_ss.sA>>>(x, p_w1h, p_w1l,
                                                               aS1, aD1);
    cudaEventRecord(g_ss.eA, g_ss.sA);

    k_count<<<(EE / 4 + 255) / 256, 256>>>(dstp);
    k_scan_lb<<<98, 1024>>>();
    k_scatter<<<(EE / 4 + 255) / 256, 256>>>(srcp, dstp);

    // join: aggregation tail needs both branches
    cudaStreamWaitEvent(0, g_ss.eA, 0);
    k_agg1<<<(NN + 7) / 8, 256>>>(b1, pw);
    k_gemm2_mma<<<(NN + 127) / 128, 256, G2_TOTAL>>>(p_o1h, p_o1l, p_w2h, p_w2l,
                                                     aS2, aD2);
    k_agg2<<<(NN + 7) / 8, 256>>>(b2, out);
}

// round 14
// speedup vs baseline: 1.1056x; 1.1008x over previous
#include <cuda_runtime.h>
#include <cuda_bf16.h>
#include <cstdint>

#define NN 100000
#define EE 1600000
#define ETOT (EE + NN)

// ---------------- scratch (static __device__ — no allocations) ----------------
__device__ uint32_t g_h1b[NN * 32];   // h1 as packed bf16x2 (col pairs)
__device__ uint32_t g_h2b[NN * 64];   // h2 as packed bf16x2 (col pairs)
__device__ float g_as1[NN * 8];
__device__ float g_ad1[NN * 8];
__device__ float g_as2[NN * 8];
__device__ float g_ad2[NN * 8];
__device__ int   g_rowptr[NN + 1];
__device__ int   g_cur[NN];
__device__ int   g_csr[ETOT];
__device__ int   g_bagg[98];
__device__ int   g_cnt;
__device__ __nv_bfloat16 g_w1h[64 * 512];   // W1^T bf16 [n][k]
__device__ __nv_bfloat16 g_w2h[128 * 64];   // W2^T bf16 [n][k]
__device__ __nv_bfloat16 g_o1h[NN * 64];    // out1 bf16

// ---------------- streams/events (static init, before harness checkpoints) -----
struct SideStreams {
    cudaStream_t sA;
    cudaEvent_t e0, eA;
    SideStreams() {
        cudaStreamCreateWithFlags(&sA, cudaStreamNonBlocking);
        cudaEventCreateWithFlags(&e0, cudaEventDisableTiming);
        cudaEventCreateWithFlags(&eA, cudaEventDisableTiming);
    }
};
static SideStreams g_ss;

// ---------------- warp mma ------------------------------------------------------
__device__ __forceinline__ void mma16816(float* c, uint32_t a0, uint32_t a1,
                                         uint32_t a2, uint32_t a3,
                                         uint32_t b0, uint32_t b1) {
    asm volatile(
        "mma.sync.aligned.m16n8k16.row.col.f32.bf16.bf16.f32 "
        "{%0,%1,%2,%3}, {%4,%5,%6,%7}, {%8,%9}, {%0,%1,%2,%3};"
        : "+f"(c[0]), "+f"(c[1]), "+f"(c[2]), "+f"(c[3])
        : "r"(a0), "r"(a1), "r"(a2), "r"(a3), "r"(b0), "r"(b1));
}

// ---------------- prep: weight bf16 split + counter resets ----------------------
__global__ void k_prep(const float* __restrict__ W1, const float* __restrict__ W2) {
    int idx = blockIdx.x * 256 + threadIdx.x;
    if (idx < NN) g_cur[idx] = 0;
    if (idx == 0) g_cnt = 0;
    if (idx < 512 * 64) {
        int k = idx >> 6, n = idx & 63;
        g_w1h[n * 512 + k] = __float2bfloat16(W1[idx]);
    }
    if (idx < 64 * 128) {
        int k = idx >> 7, n = idx & 127;
        g_w2h[n * 64 + k] = __float2bfloat16(W2[idx]);
    }
}

// ---------------- CSR build (split kernels — proven fastest) --------------------
__global__ void k_count(const int* __restrict__ dst) {
    int e4 = blockIdx.x * blockDim.x + threadIdx.x;
    if (e4 < EE / 4) {
        int4 d = *(const int4*)(dst + e4 * 4);
        atomicAdd(&g_cur[d.x], 1);
        atomicAdd(&g_cur[d.y], 1);
        atomicAdd(&g_cur[d.z], 1);
        atomicAdd(&g_cur[d.w], 1);
    }
}
__global__ void k_scan_lb() {
    __shared__ int sh[1024];
    __shared__ int s_excl;
    int t = threadIdx.x, bid = blockIdx.x;
    int i = bid * 1024 + t;
    int v = (i < NN) ? g_cur[i] + 1 : 0;  // +1 = self loop
    sh[t] = v;
    __syncthreads();
    for (int off = 1; off < 1024; off <<= 1) {
        int a = (t >= off) ? sh[t - off] : 0;
        __syncthreads();
        sh[t] += a;
        __syncthreads();
    }
    int incl = sh[t];
    if (t == 0) {
        g_bagg[bid] = sh[1023];
        __threadfence();
        atomicAdd(&g_cnt, 1);
        while (atomicAdd(&g_cnt, 0) < 98) { }
    }
    __syncthreads();
    if (t < 32) {
        int sum = 0;
        for (int base = 0; base < bid; base += 32) {
            int idx2 = base + t;
            int val = (idx2 < bid) ? g_bagg[idx2] : 0;
#pragma unroll
            for (int o = 16; o; o >>= 1) val += __shfl_xor_sync(0xffffffffu, val, o);
            sum += val;
        }
        if (t == 0) s_excl = sum;
    }
    __syncthreads();
    if (i < NN) {
        int p = s_excl + incl - v;
        g_rowptr[i] = p;
        g_csr[p] = i;
        g_cur[i] = p + 1;
    }
    if (i == 0) g_rowptr[NN] = ETOT;
}
__global__ void k_scatter(const int* __restrict__ src, const int* __restrict__ dst) {
    int e4 = blockIdx.x * blockDim.x + threadIdx.x;
    if (e4 < EE / 4) {
        int4 s = *(const int4*)(src + e4 * 4);
        int4 d = *(const int4*)(dst + e4 * 4);
        g_csr[atomicAdd(&g_cur[d.x], 1)] = s.x;
        g_csr[atomicAdd(&g_cur[d.y], 1)] = s.y;
        g_csr[atomicAdd(&g_cur[d.z], 1)] = s.z;
        g_csr[atomicAdd(&g_cur[d.w], 1)] = s.w;
    }
}

// ---------------- layer-1 GEMM via mma.sync (pure bf16), alpha fused ------------
#define A_OFF 0
#define B_OFF 36864
#define SM1_TOTAL 73728   // max(A 36864 + B 9216, C staging 256*72*4)

__global__ void __launch_bounds__(256) k_gemm1_mma(
    const float* __restrict__ x, const __nv_bfloat16* __restrict__ Wh,
    const float* __restrict__ aS, const float* __restrict__ aD) {
    extern __shared__ char smem[];
    const int tid = threadIdx.x;
    const int wid = tid >> 5, lane = tid & 31;
    const int gr = lane >> 2;
    const int kc = (lane & 3) * 2;
    const int m0 = blockIdx.x * 256;
    const int wr = wid * 32;

    float acc[2][8][4];
#pragma unroll
    for (int i = 0; i < 2; i++)
#pragma unroll
        for (int j = 0; j < 8; j++)
#pragma unroll
            for (int q = 0; q < 4; q++) acc[i][j][q] = 0.f;

    for (int kt = 0; kt < 512; kt += 64) {
        // A tile: 256 rows x 64 fp32 -> bf16
#pragma unroll
        for (int i = 0; i < 16; i++) {
            int idx = tid + 256 * i;
            int r = idx >> 4, c4 = idx & 15;
            float4 v = make_float4(0.f, 0.f, 0.f, 0.f);
            if (m0 + r < NN)
                v = *(const float4*)(x + (size_t)(m0 + r) * 512 + kt + c4 * 4);
            __nv_bfloat162 h01 = __floats2bfloat162_rn(v.x, v.y);
            __nv_bfloat162 h23 = __floats2bfloat162_rn(v.z, v.w);
            *(uint2*)(smem + A_OFF + r * 144 + c4 * 8) =
                make_uint2(*(uint32_t*)&h01, *(uint32_t*)&h23);
        }
        // B tile: 64 rows x 64 bf16
#pragma unroll
        for (int i = 0; i < 4; i++) {
            int idx = tid + 256 * i;
            int n = idx >> 4, c4 = idx & 15;
            *(uint2*)(smem + B_OFF + n * 144 + c4 * 8) =
                *(const uint2*)(Wh + n * 512 + kt + c4 * 4);
        }
        __syncthreads();
#pragma unroll
        for (int s = 0; s < 4; s++) {
            const int ks = s * 16;
            uint32_t ar[2][4];
#pragma unroll
            for (int i = 0; i < 2; i++) {
                int r0 = wr + i * 16 + gr;
                const char* pa = smem + A_OFF + (r0 * 144 + (ks + kc) * 2);
                ar[i][0] = *(const uint32_t*)(pa);
                ar[i][1] = *(const uint32_t*)(pa + 8 * 144);
                ar[i][2] = *(const uint32_t*)(pa + 16);
                ar[i][3] = *(const uint32_t*)(pa + 8 * 144 + 16);
            }
#pragma unroll
            for (int j = 0; j < 8; j++) {
                int n0 = j * 8 + gr;
                const char* pb = smem + B_OFF + (n0 * 144 + (ks + kc) * 2);
                uint32_t b0 = *(const uint32_t*)(pb);
                uint32_t b1 = *(const uint32_t*)(pb + 16);
#pragma unroll
                for (int i = 0; i < 2; i++)
                    mma16816(acc[i][j], ar[i][0], ar[i][1], ar[i][2], ar[i][3], b0, b1);
            }
        }
        __syncthreads();
    }

    float* Cs = (float*)smem;
#pragma unroll
    for (int i = 0; i < 2; i++) {
        int r0 = wr + i * 16 + gr;
#pragma unroll
        for (int j = 0; j < 8; j++) {
            int col = j * 8 + kc;
            *(float2*)&Cs[r0 * 72 + col] = make_float2(acc[i][j][0], acc[i][j][1]);
            *(float2*)&Cs[(r0 + 8) * 72 + col] = make_float2(acc[i][j][2], acc[i][j][3]);
        }
    }
    __syncthreads();

    int m = m0 + tid;
    if (m < NN) {
        const float* row = Cs + tid * 72;
#pragma unroll
        for (int c = 0; c < 64; c += 8) {
            __nv_bfloat162 t0 = __floats2bfloat162_rn(row[c + 0], row[c + 1]);
            __nv_bfloat162 t1 = __floats2bfloat162_rn(row[c + 2], row[c + 3]);
            __nv_bfloat162 t2 = __floats2bfloat162_rn(row[c + 4], row[c + 5]);
            __nv_bfloat162 t3 = __floats2bfloat162_rn(row[c + 6], row[c + 7]);
            *(uint4*)(g_h1b + (size_t)m * 32 + c / 2) =
                make_uint4(*(uint32_t*)&t0, *(uint32_t*)&t1,
                           *(uint32_t*)&t2, *(uint32_t*)&t3);
        }
        float s[8], t[8];
#pragma unroll
        for (int h = 0; h < 8; h++) { s[h] = 0.f; t[h] = 0.f; }
#pragma unroll
        for (int h = 0; h < 8; h++)
#pragma unroll
            for (int c = 0; c < 8; c++) {
                float v = row[h * 8 + c];
                s[h] = fmaf(v, aS[h * 8 + c], s[h]);
                t[h] = fmaf(v, aD[h * 8 + c], t[h]);
            }
        *(float4*)(g_as1 + (size_t)m * 8) = make_float4(s[0], s[1], s[2], s[3]);
        *(float4*)(g_as1 + (size_t)m * 8 + 4) = make_float4(s[4], s[5], s[6], s[7]);
        *(float4*)(g_ad1 + (size_t)m * 8) = make_float4(t[0], t[1], t[2], t[3]);
        *(float4*)(g_ad1 + (size_t)m * 8 + 4) = make_float4(t[4], t[5], t[6], t[7]);
    }
}

// ---------------- layer-2 GEMM via mma.sync (pure bf16), alpha fused ------------
#define G2_A 0
#define G2_B 18432
#define G2_TOTAL 67584    // max(A+B 36864, C staging 128*132*4)

__global__ void __launch_bounds__(256) k_gemm2_mma(
    const __nv_bfloat16* __restrict__ Ah, const __nv_bfloat16* __restrict__ Bh,
    const float* __restrict__ aS, const float* __restrict__ aD) {
    extern __shared__ char smem[];
    const int tid = threadIdx.x;
    const int wid = tid >> 5, lane = tid & 31;
    const int gr = lane >> 2;
    const int kc = (lane & 3) * 2;
    const int wm = wid & 3, wn = wid >> 2;
    const int m0 = blockIdx.x * 128;

#pragma unroll
    for (int i = 0; i < 8; i++) {
        int idx = tid + 256 * i;
        int r = idx >> 4, c4 = idx & 15;
        uint2 vh = make_uint2(0u, 0u);
        if (m0 + r < NN)
            vh = *(const uint2*)(Ah + (size_t)(m0 + r) * 64 + c4 * 4);
        *(uint2*)(smem + G2_A + r * 144 + c4 * 8) = vh;
    }
#pragma unroll
    for (int i = 0; i < 8; i++) {
        int idx = tid + 256 * i;
        int n = idx >> 4, c4 = idx & 15;
        *(uint2*)(smem + G2_B + n * 144 + c4 * 8) =
            *(const uint2*)(Bh + n * 64 + c4 * 4);
    }
    __syncthreads();

    float acc[2][8][4];
#pragma unroll
    for (int i = 0; i < 2; i++)
#pragma unroll
        for (int j = 0; j < 8; j++)
#pragma unroll
            for (int q = 0; q < 4; q++) acc[i][j][q] = 0.f;

#pragma unroll
    for (int s = 0; s < 4; s++) {
        const int ks = s * 16;
        uint32_t ar[2][4];
#pragma unroll
        for (int i = 0; i < 2; i++) {
            int r0 = wm * 32 + i * 16 + gr;
            const char* pa = smem + G2_A + (r0 * 144 + (ks + kc) * 2);
            ar[i][0] = *(const uint32_t*)(pa);
            ar[i][1] = *(const uint32_t*)(pa + 8 * 144);
            ar[i][2] = *(const uint32_t*)(pa + 16);
            ar[i][3] = *(const uint32_t*)(pa + 8 * 144 + 16);
        }
#pragma unroll
        for (int j = 0; j < 8; j++) {
            int n0 = wn * 64 + j * 8 + gr;
            const char* pb = smem + G2_B + (n0 * 144 + (ks + kc) * 2);
            uint32_t b0 = *(const uint32_t*)(pb);
            uint32_t b1 = *(const uint32_t*)(pb + 16);
#pragma unroll
            for (int i = 0; i < 2; i++)
                mma16816(acc[i][j], ar[i][0], ar[i][1], ar[i][2], ar[i][3], b0, b1);
        }
    }
    __syncthreads();

    float* Cs = (float*)smem;
#pragma unroll
    for (int i = 0; i < 2; i++) {
        int r0 = wm * 32 + i * 16 + gr;
#pragma unroll
        for (int j = 0; j < 8; j++) {
            int col = wn * 64 + j * 8 + kc;
            *(float2*)&Cs[r0 * 132 + col] = make_float2(acc[i][j][0], acc[i][j][1]);
            *(float2*)&Cs[(r0 + 8) * 132 + col] = make_float2(acc[i][j][2], acc[i][j][3]);
        }
    }
    __syncthreads();

    int r = tid >> 1, chalf = (tid & 1) * 64;
    int m = m0 + r;
    if (m < NN) {
        const float* row = Cs + r * 132 + chalf;
#pragma unroll
        for (int c = 0; c < 64; c += 8) {
            __nv_bfloat162 t0 = __floats2bfloat162_rn(row[c + 0], row[c + 1]);
            __nv_bfloat162 t1 = __floats2bfloat162_rn(row[c + 2], row[c + 3]);
            __nv_bfloat162 t2 = __floats2bfloat162_rn(row[c + 4], row[c + 5]);
            __nv_bfloat162 t3 = __floats2bfloat162_rn(row[c + 6], row[c + 7]);
            *(uint4*)(g_h2b + (size_t)m * 64 + (tid & 1) * 32 + c / 2) =
                make_uint4(*(uint32_t*)&t0, *(uint32_t*)&t1,
                           *(uint32_t*)&t2, *(uint32_t*)&t3);
        }
        int hb = (tid & 1) * 4;
        float s[4], t[4];
#pragma unroll
        for (int q = 0; q < 4; q++) { s[q] = 0.f; t[q] = 0.f; }
#pragma unroll
        for (int q = 0; q < 4; q++) {
            int hh = hb + q;
#pragma unroll
            for (int c = 0; c < 16; c++) {
                float v = row[q * 16 + c];
                s[q] = fmaf(v, aS[hh * 16 + c], s[q]);
                t[q] = fmaf(v, aD[hh * 16 + c], t[q]);
            }
        }
        *(float4*)(g_as2 + (size_t)m * 8 + hb) = make_float4(s[0], s[1], s[2], s[3]);
        *(float4*)(g_ad2 + (size_t)m * 8 + hb) = make_float4(t[0], t[1], t[2], t[3]);
    }
}

// ---------------- layer-1 aggregation (bf16 h1, col-pair lanes) -----------------
__global__ void k_agg1(const float* __restrict__ bias, const float* __restrict__ preluw) {
    __shared__ float s_ex[8][32][8];
    __shared__ int s_sr[8][32];
    int warp = threadIdx.x >> 5, lane = threadIdx.x & 31;
    int n = blockIdx.x * 8 + warp;
    if (n >= NN) return;
    int s = g_rowptr[n], e2 = g_rowptr[n + 1];

    float adv[8];
    {
        float4 a0 = *(const float4*)(g_ad1 + n * 8);
        float4 a1 = *(const float4*)(g_ad1 + n * 8 + 4);
        adv[0] = a0.x; adv[1] = a0.y; adv[2] = a0.z; adv[3] = a0.w;
        adv[4] = a1.x; adv[5] = a1.y; adv[6] = a1.z; adv[7] = a1.w;
    }
    float den[8];
#pragma unroll
    for (int k = 0; k < 8; k++) den[k] = 0.f;
    float a0c = 0.f, a1c = 0.f;
    const int hown = lane >> 2;
    for (int base = s; base < e2; base += 32) {
        int idx = base + lane;
        int cnt = min(32, e2 - base);
        int sr = 0;
        float ex[8];
#pragma unroll
        for (int k = 0; k < 8; k++) ex[k] = 0.f;
        if (idx < e2) {
            sr = g_csr[idx];
            float4 a0 = *(const float4*)(g_as1 + sr * 8);
            float4 a1 = *(const float4*)(g_as1 + sr * 8 + 4);
            float av[8] = {a0.x, a0.y, a0.z, a0.w, a1.x, a1.y, a1.z, a1.w};
#pragma unroll
            for (int k = 0; k < 8; k++) {
                float e = av[k] + adv[k];
                e = e >= 0.f ? e : 0.2f * e;
                ex[k] = __expf(e);
                den[k] += ex[k];
            }
        }
        s_sr[warp][lane] = sr;
        *(float4*)&s_ex[warp][lane][0] = make_float4(ex[0], ex[1], ex[2], ex[3]);
        *(float4*)&s_ex[warp][lane][4] = make_float4(ex[4], ex[5], ex[6], ex[7]);
        __syncwarp();
        int cnt4 = (cnt + 3) & ~3;
        for (int j = 0; j < cnt4; j += 4) {
            int s0 = s_sr[warp][j + 0], s1 = s_sr[warp][j + 1];
            int s2 = s_sr[warp][j + 2], s3 = s_sr[warp][j + 3];
            uint32_t q0 = g_h1b[(size_t)s0 * 32 + lane];
            uint32_t q1 = g_h1b[(size_t)s1 * 32 + lane];
            uint32_t q2 = g_h1b[(size_t)s2 * 32 + lane];
            uint32_t q3 = g_h1b[(size_t)s3 * 32 + lane];
            float e0 = s_ex[warp][j + 0][hown];
            float e1 = s_ex[warp][j + 1][hown];
            float e2w = s_ex[warp][j + 2][hown];
            float e3 = s_ex[warp][j + 3][hown];
            float2 f0 = __bfloat1622float2(*(__nv_bfloat162*)&q0);
            float2 f1 = __bfloat1622float2(*(__nv_bfloat162*)&q1);
            float2 f2 = __bfloat1622float2(*(__nv_bfloat162*)&q2);
            float2 f3 = __bfloat1622float2(*(__nv_bfloat162*)&q3);
            a0c = fmaf(e0, f0.x, a0c); a1c = fmaf(e0, f0.y, a1c);
            a0c = fmaf(e1, f1.x, a0c); a1c = fmaf(e1, f1.y, a1c);
            a0c = fmaf(e2w, f2.x, a0c); a1c = fmaf(e2w, f2.y, a1c);
            a0c = fmaf(e3, f3.x, a0c); a1c = fmaf(e3, f3.y, a1c);
        }
        __syncwarp();
    }
#pragma unroll
    for (int k = 0; k < 8; k++)
#pragma unroll
        for (int off = 16; off; off >>= 1)
            den[k] += __shfl_xor_sync(0xffffffffu, den[k], off);

    float d = (hown == 0) ? den[0] : (hown == 1) ? den[1] : (hown == 2) ? den[2]
            : (hown == 3) ? den[3] : (hown == 4) ? den[4] : (hown == 5) ? den[5]
            : (hown == 6) ? den[6] : den[7];
    float pw = *preluw;
    float v0 = a0c / d + bias[2 * lane];
    float v1 = a1c / d + bias[2 * lane + 1];
    v0 = v0 >= 0.f ? v0 : pw * v0;
    v1 = v1 >= 0.f ? v1 : pw * v1;
    __nv_bfloat162 hi = __floats2bfloat162_rn(v0, v1);
    ((uint32_t*)(g_o1h + (size_t)n * 64))[lane] = *(uint32_t*)&hi;
}

// ---------------- layer-2 aggregation (bf16 h2) + mean + bias + log_softmax -----
__global__ void k_agg2(const float* __restrict__ bias2, float* __restrict__ out) {
    __shared__ float s_ex[8][32][8];
    __shared__ int s_sr[8][32];
    int warp = threadIdx.x >> 5, lane = threadIdx.x & 31;
    int n = blockIdx.x * 8 + warp;
    if (n >= NN) return;
    int s = g_rowptr[n], e2 = g_rowptr[n + 1];

    float adv[8];
    {
        float4 a0 = *(const float4*)(g_ad2 + n * 8);
        float4 a1 = *(const float4*)(g_ad2 + n * 8 + 4);
        adv[0] = a0.x; adv[1] = a0.y; adv[2] = a0.z; adv[3] = a0.w;
        adv[4] = a1.x; adv[5] = a1.y; adv[6] = a1.z; adv[7] = a1.w;
    }
    float den[8];
#pragma unroll
    for (int k = 0; k < 8; k++) den[k] = 0.f;
    float a00 = 0.f, a01 = 0.f, a10 = 0.f, a11 = 0.f;
    const int ha = lane >> 3, hb = 4 + (lane >> 3);
    for (int base = s; base < e2; base += 32) {
        int idx = base + lane;
        int cnt = min(32, e2 - base);
        int sr = 0;
        float ex[8];
#pragma unroll
        for (int k = 0; k < 8; k++) ex[k] = 0.f;
        if (idx < e2) {
            sr = g_csr[idx];
            float4 a0 = *(const float4*)(g_as2 + sr * 8);
            float4 a1 = *(const float4*)(g_as2 + sr * 8 + 4);
            float av[8] = {a0.x, a0.y, a0.z, a0.w, a1.x, a1.y, a1.z, a1.w};
#pragma unroll
            for (int k = 0; k < 8; k++) {
                float e = av[k] + adv[k];
                e = e >= 0.f ? e : 0.2f * e;
                ex[k] = __expf(e);
                den[k] += ex[k];
            }
        }
        s_sr[warp][lane] = sr;
        *(float4*)&s_ex[warp][lane][0] = make_float4(ex[0], ex[1], ex[2], ex[3]);
        *(float4*)&s_ex[warp][lane][4] = make_float4(ex[4], ex[5], ex[6], ex[7]);
        __syncwarp();
        int cnt4 = (cnt + 3) & ~3;
        for (int j = 0; j < cnt4; j += 4) {
            int s0 = s_sr[warp][j + 0], s1 = s_sr[warp][j + 1];
            int s2 = s_sr[warp][j + 2], s3 = s_sr[warp][j + 3];
            const uint32_t* p0 = g_h2b + (size_t)s0 * 64;
            const uint32_t* p1 = g_h2b + (size_t)s1 * 64;
            const uint32_t* p2 = g_h2b + (size_t)s2 * 64;
            const uint32_t* p3 = g_h2b + (size_t)s3 * 64;
            uint32_t qa0 = p0[lane], qb0 = p0[lane + 32];
            uint32_t qa1 = p1[lane], qb1 = p1[lane + 32];
            uint32_t qa2 = p2[lane], qb2 = p2[lane + 32];
            uint32_t qa3 = p3[lane], qb3 = p3[lane + 32];
            float ea0 = s_ex[warp][j + 0][ha], eb0 = s_ex[warp][j + 0][hb];
            float ea1 = s_ex[warp][j + 1][ha], eb1 = s_ex[warp][j + 1][hb];
            float ea2 = s_ex[warp][j + 2][ha], eb2 = s_ex[warp][j + 2][hb];
            float ea3 = s_ex[warp][j + 3][ha], eb3 = s_ex[warp][j + 3][hb];
            float2 fa0 = __bfloat1622float2(*(__nv_bfloat162*)&qa0);
            float2 fb0 = __bfloat1622float2(*(__nv_bfloat162*)&qb0);
            float2 fa1 = __bfloat1622float2(*(__nv_bfloat162*)&qa1);
            float2 fb1 = __bfloat1622float2(*(__nv_bfloat162*)&qb1);
            float2 fa2 = __bfloat1622float2(*(__nv_bfloat162*)&qa2);
            float2 fb2 = __bfloat1622float2(*(__nv_bfloat162*)&qb2);
            float2 fa3 = __bfloat1622float2(*(__nv_bfloat162*)&qa3);
            float2 fb3 = __bfloat1622float2(*(__nv_bfloat162*)&qb3);
            a00 = fmaf(ea0, fa0.x, a00); a01 = fmaf(ea0, fa0.y, a01);
            a10 = fmaf(eb0, fb0.x, a10); a11 = fmaf(eb0, fb0.y, a11);
            a00 = fmaf(ea1, fa1.x, a00); a01 = fmaf(ea1, fa1.y, a01);
            a10 = fmaf(eb1, fb1.x, a10); a11 = fmaf(eb1, fb1.y, a11);
            a00 = fmaf(ea2, fa2.x, a00); a01 = fmaf(ea2, fa2.y, a01);
            a10 = fmaf(eb2, fb2.x, a10); a11 = fmaf(eb2, fb2.y, a11);
            a00 = fmaf(ea3, fa3.x, a00); a01 = fmaf(ea3, fa3.y, a01);
            a10 = fmaf(eb3, fb3.x, a10); a11 = fmaf(eb3, fb3.y, a11);
        }
        __syncwarp();
    }
#pragma unroll
    for (int k = 0; k < 8; k++)
#pragma unroll
        for (int off = 16; off; off >>= 1)
            den[k] += __shfl_xor_sync(0xffffffffu, den[k], off);

    float da = (lane < 8) ? den[0] : (lane < 16) ? den[1] : (lane < 24) ? den[2] : den[3];
    float db = (lane < 8) ? den[4] : (lane < 16) ? den[5] : (lane < 24) ? den[6] : den[7];
    float v0 = a00 / da + a10 / db;
    float v1 = a01 / da + a11 / db;
    v0 += __shfl_xor_sync(0xffffffffu, v0, 8);
    v0 += __shfl_xor_sync(0xffffffffu, v0, 16);
    v1 += __shfl_xor_sync(0xffffffffu, v1, 8);
    v1 += __shfl_xor_sync(0xffffffffu, v1, 16);
    int cp = lane & 7;
    v0 = v0 * 0.125f + bias2[2 * cp];
    v1 = v1 * 0.125f + bias2[2 * cp + 1];
    float mx = fmaxf(v0, v1);
#pragma unroll
    for (int off = 4; off; off >>= 1) mx = fmaxf(mx, __shfl_xor_sync(0xffffffffu, mx, off));
    float se = __expf(v0 - mx) + __expf(v1 - mx);
#pragma unroll
    for (int off = 4; off; off >>= 1) se += __shfl_xor_sync(0xffffffffu, se, off);
    float ls = __logf(se);
    if (lane < 8)
        *(float2*)(out + (size_t)n * 16 + 2 * cp) =
            make_float2(v0 - mx - ls, v1 - mx - ls);
}

// ---------------- launcher ------------------------------------------------------
extern "C" void kernel_launch(void* const* d_in, const int* in_sizes, int n_in,
                              void* d_out, int out_size) {
    const float* x   = (const float*)d_in[0];
    const int*   ei  = (const int*)d_in[1];
    const float* W1  = (const float*)d_in[2];
    const float* aS1 = (const float*)d_in[3];
    const float* aD1 = (const float*)d_in[4];
    const float* b1  = (const float*)d_in[5];
    const float* pw  = (const float*)d_in[6];
    const float* W2  = (const float*)d_in[7];
    const float* aS2 = (const float*)d_in[8];
    const float* aD2 = (const float*)d_in[9];
    const float* b2  = (const float*)d_in[10];
    float* out = (float*)d_out;

    const int* srcp = ei;
    const int* dstp = ei + EE;

    __nv_bfloat16 *p_w1h, *p_w2h, *p_o1h;
    cudaGetSymbolAddress((void**)&p_w1h, g_w1h);
    cudaGetSymbolAddress((void**)&p_w2h, g_w2h);
    cudaGetSymbolAddress((void**)&p_o1h, g_o1h);

    cudaFuncSetAttribute(k_gemm1_mma, cudaFuncAttributeMaxDynamicSharedMemorySize,
                         SM1_TOTAL);
    cudaFuncSetAttribute(k_gemm2_mma, cudaFuncAttributeMaxDynamicSharedMemorySize,
                         G2_TOTAL);

    // 1: prep (weights bf16 + counter resets)
    k_prep<<<(NN + 255) / 256, 256>>>(W1, W2);

    // fork: GEMM1 on side stream, split CSR build on default stream
    cudaEventRecord(g_ss.e0, 0);
    cudaStreamWaitEvent(g_ss.sA, g_ss.e0, 0);
    k_gemm1_mma<<<(NN + 255) / 256, 256, SM1_TOTAL, g_ss.sA>>>(x, p_w1h, aS1, aD1);
    cudaEventRecord(g_ss.eA, g_ss.sA);

    k_count<<<(EE / 4 + 255) / 256, 256>>>(dstp);
    k_scan_lb<<<98, 1024>>>();
    k_scatter<<<(EE / 4 + 255) / 256, 256>>>(srcp, dstp);

    // join: aggregation tail needs both branches
    cudaStreamWaitEvent(0, g_ss.eA, 0);
    k_agg1<<<(NN + 7) / 8, 256>>>(b1, pw);
    k_gemm2_mma<<<(NN + 127) / 128, 256, G2_TOTAL>>>(p_o1h, p_w2h, aS2, aD2);
    k_agg2<<<(NN + 7) / 8, 256>>>(b2, out);
}